// round 13
// baseline (speedup 1.0000x reference)
#include <cuda_runtime.h>
#include <cstdint>
#include <cstddef>

#define NP 200000
#define NA 100000
#define EC 4000000
#define EW 2000000

// ---------------- device scratch (allocation-free) ----------------
__device__ float g_xls[(size_t)NP * 64];   // raw x_paper @ gcn_W
__device__ float g_P  [(size_t)NP * 64];   // sage_Wr root term
__device__ float g_G  [(size_t)NP * 64];   // gcn gather output (standalone)
__device__ float g_SA [(size_t)NP * 64];   // sage neighbor mean
__device__ float g_XS [(size_t)NP * 64];   // gat L0 source feats (paper)
__device__ float g_XS1[(size_t)NP * 64];   // gat L1 source feats (paper)
__device__ float g_XD [(size_t)NA * 64];   // gat dst feats (author)
__device__ float g_xp1[(size_t)NP * 64];   // x_paper after layer 0
__device__ float g_xa1[(size_t)NA * 64];   // x_author after layer 0/1
__device__ float g_Wcat[128 * 128];        // [sage_Wr0 | gat_Ws0]
__device__ float g_dis [NP];
__device__ float g_asrc[NP],  g_adst[NA];
__device__ float g_asrc1[NP], g_adst1[NA];
__device__ int g_degC[NP], g_degWp[NP], g_degWa[NA];
__device__ int g_offC[NP], g_offWp[NP], g_offWa[NA];
__device__ int g_curC[NP], g_curWp[NP], g_curWa[NA];
__device__ int g_bsumA[512], g_bsumB[512];
__device__ int g_csrC[EC], g_csrWp[EW], g_csrWa[EW];

// ---------------- utility kernels ----------------
__global__ void k_zero_i(int* p, int n) {
    int i = blockIdx.x * blockDim.x + threadIdx.x;
    if (i < n) p[i] = 0;
}
__global__ void k_count(const int* __restrict__ idx, int* cnt, int E) {
    int i = blockIdx.x * blockDim.x + threadIdx.x;
    if (i < E) atomicAdd(&cnt[idx[i]], 1);
}
__global__ void k_dis(const int* __restrict__ cnt, float* dis, int n) {
    int i = blockIdx.x * blockDim.x + threadIdx.x;
    if (i < n) dis[i] = rsqrtf((float)cnt[i] + 1.0f);
}
// concat two 128x64 weights into 128x128
__global__ void k_wcat2(const float* __restrict__ w0, const float* __restrict__ w1,
                        float* __restrict__ out) {
    int i = blockIdx.x * blockDim.x + threadIdx.x;
    if (i >= 128 * 128) return;
    int k = i >> 7, c = i & 127;
    out[i] = (c < 64) ? w0[k * 64 + c] : w1[k * 64 + (c - 64)];
}

// ---------------- scan (3-phase, blocks of 512) ----------------
__global__ void k_scan1(const int* __restrict__ deg, int* off, int* bsum, int n) {
    __shared__ int sh[512];
    int t = threadIdx.x, i = blockIdx.x * 512 + t;
    int v = (i < n) ? deg[i] : 0;
    sh[t] = v; __syncthreads();
    #pragma unroll
    for (int o = 1; o < 512; o <<= 1) {
        int x = (t >= o) ? sh[t - o] : 0;
        __syncthreads(); sh[t] += x; __syncthreads();
    }
    if (i < n) off[i] = sh[t] - v;
    if (t == 511) bsum[blockIdx.x] = sh[511];
}
__global__ void k_scan2(int* bsum, int nb) {
    __shared__ int sh[512];
    int t = threadIdx.x;
    int v = (t < nb) ? bsum[t] : 0;
    sh[t] = v; __syncthreads();
    #pragma unroll
    for (int o = 1; o < 512; o <<= 1) {
        int x = (t >= o) ? sh[t - o] : 0;
        __syncthreads(); sh[t] += x; __syncthreads();
    }
    if (t < nb) bsum[t] = sh[t] - v;
}
__global__ void k_scan3(int* off, int* cur, const int* __restrict__ bsum, int n) {
    int i = blockIdx.x * blockDim.x + threadIdx.x;
    if (i < n) { int v = off[i] + bsum[i >> 9]; off[i] = v; cur[i] = v; }
}
__global__ void k_fill(const int* __restrict__ dst, const int* __restrict__ src,
                       int* cur, int* csr, int E) {
    int i = blockIdx.x * blockDim.x + threadIdx.x;
    if (i < E) {
        int pos = atomicAdd(&cur[dst[i]], 1);
        csr[pos] = src[i];
    }
}

// ---------------- gathers (1 warp / node, 2 cols / lane) ----------------
// G = dis[w] * (sum_{nbr} dis[s]*xls[s] + dis[w]*xls[w])   (standalone write)
__global__ void k_gcn_gather(const int* __restrict__ off, const int* __restrict__ csr,
                             const float* __restrict__ xls, const float* __restrict__ dis,
                             float* __restrict__ G, int n, int E) {
    int w = (blockIdx.x * blockDim.x + threadIdx.x) >> 5;
    int lane = threadIdx.x & 31;
    if (w >= n) return;
    int beg = off[w], end = (w == n - 1) ? E : off[w + 1];
    float a0 = 0.f, a1 = 0.f;
    int t = beg;
    for (; t + 4 <= end; t += 4) {
        int s0 = __ldg(&csr[t]),     s1 = __ldg(&csr[t + 1]);
        int s2 = __ldg(&csr[t + 2]), s3 = __ldg(&csr[t + 3]);
        float d0 = __ldg(&dis[s0]), d1 = __ldg(&dis[s1]);
        float d2 = __ldg(&dis[s2]), d3 = __ldg(&dis[s3]);
        float b0 = xls[s0 * 64 + lane],      c0 = xls[s0 * 64 + 32 + lane];
        float b1 = xls[s1 * 64 + lane],      c1 = xls[s1 * 64 + 32 + lane];
        float b2 = xls[s2 * 64 + lane],      c2 = xls[s2 * 64 + 32 + lane];
        float b3 = xls[s3 * 64 + lane],      c3 = xls[s3 * 64 + 32 + lane];
        a0 += (d0 * b0 + d1 * b1) + (d2 * b2 + d3 * b3);
        a1 += (d0 * c0 + d1 * c1) + (d2 * c2 + d3 * c3);
    }
    for (; t < end; t++) {
        int s = __ldg(&csr[t]);
        float d = __ldg(&dis[s]);
        a0 += d * xls[s * 64 + lane];
        a1 += d * xls[s * 64 + 32 + lane];
    }
    float dd = dis[w];
    G[(size_t)w * 64 + lane]      = dd * (a0 + dd * xls[w * 64 + lane]);
    G[(size_t)w * 64 + 32 + lane] = dd * (a1 + dd * xls[w * 64 + 32 + lane]);
}

__global__ void k_sage_gather(const int* __restrict__ off, const int* __restrict__ csr,
                              const float* __restrict__ xa, float* __restrict__ SA,
                              int n, int E) {
    int w = (blockIdx.x * blockDim.x + threadIdx.x) >> 5;
    int lane = threadIdx.x & 31;
    if (w >= n) return;
    int beg = off[w], end = (w == n - 1) ? E : off[w + 1];
    float a0 = 0.f, a1 = 0.f;
    int t = beg;
    for (; t + 4 <= end; t += 4) {
        int s0 = __ldg(&csr[t]),     s1 = __ldg(&csr[t + 1]);
        int s2 = __ldg(&csr[t + 2]), s3 = __ldg(&csr[t + 3]);
        float b0 = xa[s0 * 64 + lane],      c0 = xa[s0 * 64 + 32 + lane];
        float b1 = xa[s1 * 64 + lane],      c1 = xa[s1 * 64 + 32 + lane];
        float b2 = xa[s2 * 64 + lane],      c2 = xa[s2 * 64 + 32 + lane];
        float b3 = xa[s3 * 64 + lane],      c3 = xa[s3 * 64 + 32 + lane];
        a0 += (b0 + b1) + (b2 + b3);
        a1 += (c0 + c1) + (c2 + c3);
    }
    for (; t < end; t++) {
        int s = __ldg(&csr[t]);
        a0 += xa[s * 64 + lane];
        a1 += xa[s * 64 + 32 + lane];
    }
    float r = 1.0f / fmaxf((float)(end - beg), 1.0f);
    SA[(size_t)w * 64 + lane]      = a0 * r;
    SA[(size_t)w * 64 + 32 + lane] = a1 * r;
}

__global__ void k_gat_gather(const int* __restrict__ off, const int* __restrict__ csr,
                             const float* __restrict__ asrc, const float* __restrict__ adst,
                             const float* __restrict__ XS, const float* __restrict__ bias,
                             float* __restrict__ out, int n, int E) {
    int w = (blockIdx.x * blockDim.x + threadIdx.x) >> 5;
    int lane = threadIdx.x & 31;
    if (w >= n) return;
    int beg = off[w], end = (w == n - 1) ? E : off[w + 1];
    float ad = adst[w];
    float den = 0.f, a0 = 0.f, a1 = 0.f;
    int t = beg;
    for (; t + 4 <= end; t += 4) {
        int p0 = __ldg(&csr[t]),     p1 = __ldg(&csr[t + 1]);
        int p2 = __ldg(&csr[t + 2]), p3 = __ldg(&csr[t + 3]);
        float e0 = asrc[p0] + ad; e0 = (e0 > 0.f) ? e0 : 0.2f * e0;
        float e1 = asrc[p1] + ad; e1 = (e1 > 0.f) ? e1 : 0.2f * e1;
        float e2 = asrc[p2] + ad; e2 = (e2 > 0.f) ? e2 : 0.2f * e2;
        float e3 = asrc[p3] + ad; e3 = (e3 > 0.f) ? e3 : 0.2f * e3;
        float x0 = __expf(e0), x1 = __expf(e1), x2 = __expf(e2), x3 = __expf(e3);
        float b0 = XS[p0 * 64 + lane],      c0 = XS[p0 * 64 + 32 + lane];
        float b1 = XS[p1 * 64 + lane],      c1 = XS[p1 * 64 + 32 + lane];
        float b2 = XS[p2 * 64 + lane],      c2 = XS[p2 * 64 + 32 + lane];
        float b3 = XS[p3 * 64 + lane],      c3 = XS[p3 * 64 + 32 + lane];
        den += (x0 + x1) + (x2 + x3);
        a0 += (x0 * b0 + x1 * b1) + (x2 * b2 + x3 * b3);
        a1 += (x0 * c0 + x1 * c1) + (x2 * c2 + x3 * c3);
    }
    for (; t < end; t++) {
        int p = __ldg(&csr[t]);
        float e = asrc[p] + ad; e = (e > 0.f) ? e : 0.2f * e;
        float x = __expf(e);
        den += x;
        a0 += x * XS[p * 64 + lane];
        a1 += x * XS[p * 64 + 32 + lane];
    }
    float r = (den > 0.f) ? (1.0f / den) : 0.f;
    float o0 = a0 * r + bias[lane];
    float o1 = a1 * r + bias[lane + 32];
    out[(size_t)w * 64 + lane]      = fmaxf(o0, 0.f);
    out[(size_t)w * 64 + 32 + lane] = fmaxf(o1, 0.f);
}

// ---------------- cp.async double-buffered f32x2 GEMM ----------------
// MODE: 0 plain | 2 comb2 (relu(acc+addsrc+addsrc2+b0+b1)) | 3 dot | 4 bias
//       5 split (N=128: cols 0-63 -> Y, 64-127 -> Y2 + dot(av) -> dotout)
#define M_PLAIN 0
#define M_COMB2 2
#define M_DOT   3
#define M_BIAS  4
#define M_SPLIT 5
#define XSTR 36
#define XSZ  (128 * XSTR)

template <int K, int N>
constexpr int gemm_smem_bytes() { return (2 * XSZ + 2 * 32 * N) * 4; }

template <int K, int N, int MODE, int MAXB>
__global__ void __launch_bounds__(256, MAXB) k_gemm2(
        const float* __restrict__ X, const float* __restrict__ W,
        const float* __restrict__ b0, const float* __restrict__ b1,
        const float* __restrict__ addsrc, const float* __restrict__ addsrc2,
        const float* __restrict__ av, float* __restrict__ dotout,
        float* __restrict__ Y, float* __restrict__ Y2, int M) {
    constexpr int CPT = N / 8;
    constexpr int QP  = CPT / 2;
    constexpr int NCH = K / 32;
    extern __shared__ __align__(16) float smemf[];
    float* Xsb[2] = { smemf, smemf + XSZ };
    float* Wsb[2] = { smemf + 2 * XSZ, smemf + 2 * XSZ + 32 * N };
    unsigned xs_u32[2], ws_u32[2];
    xs_u32[0] = (unsigned)__cvta_generic_to_shared(Xsb[0]);
    xs_u32[1] = (unsigned)__cvta_generic_to_shared(Xsb[1]);
    ws_u32[0] = (unsigned)__cvta_generic_to_shared(Wsb[0]);
    ws_u32[1] = (unsigned)__cvta_generic_to_shared(Wsb[1]);

    int tid = threadIdx.x;
    int tx = tid & 7, ty = tid >> 3;
    int base = blockIdx.x * 128;

    auto stage = [&](int c, int b) {
        int kc = c * 32;
        #pragma unroll
        for (int j = 0; j < 4; j++) {
            int v = tid + j * 256;
            int r = v >> 3;
            int k0 = (v & 7) * 4;
            int rr = base + r;
            const float* src = X + (size_t)(rr < M ? rr : 0) * K + kc + k0;
            unsigned ssize = (rr < M) ? 16u : 0u;
            unsigned daddr = xs_u32[b] + (unsigned)(r * XSTR + k0) * 4u;
            asm volatile("cp.async.cg.shared.global [%0], [%1], 16, %2;"
                         :: "r"(daddr), "l"(src), "r"(ssize));
        }
        #pragma unroll
        for (int j = 0; j < N / 32; j++) {
            int v = tid + j * 256;
            int r = (v * 4) / N;
            int cc = (v * 4) % N;
            const float* src = W + (size_t)(kc + r) * N + cc;
            unsigned daddr = ws_u32[b] + (unsigned)(r * N + cc) * 4u;
            asm volatile("cp.async.cg.shared.global [%0], [%1], 16;"
                         :: "r"(daddr), "l"(src));
        }
    };

    unsigned long long accv[4][QP];
    #pragma unroll
    for (int i = 0; i < 4; i++)
        #pragma unroll
        for (int q = 0; q < QP; q++) accv[i][q] = 0ull;

    stage(0, 0);
    asm volatile("cp.async.commit_group;");

    for (int c = 0; c < NCH; c++) {
        int buf = c & 1;
        if (c + 1 < NCH) {
            stage(c + 1, (c + 1) & 1);
            asm volatile("cp.async.commit_group;");
            asm volatile("cp.async.wait_group 1;");
        } else {
            asm volatile("cp.async.wait_group 0;");
        }
        __syncthreads();
        const float* Xc = Xsb[buf];
        const float* Wc = Wsb[buf];
        #pragma unroll
        for (int k = 0; k < 32; k++) {
            unsigned long long a[4];
            #pragma unroll
            for (int i = 0; i < 4; i++) {
                unsigned a32 = *(const unsigned*)&Xc[(ty + 32 * i) * XSTR + k];
                asm("mov.b64 %0, {%1, %1};" : "=l"(a[i]) : "r"(a32));
            }
            #pragma unroll
            for (int h = 0; h < QP / 2; h++) {
                ulonglong2 wp = *(const ulonglong2*)&Wc[k * N + tx * CPT + h * 4];
                #pragma unroll
                for (int i = 0; i < 4; i++) {
                    asm("fma.rn.f32x2 %0, %1, %2, %0;"
                        : "+l"(accv[i][2 * h]) : "l"(a[i]), "l"(wp.x));
                    asm("fma.rn.f32x2 %0, %1, %2, %0;"
                        : "+l"(accv[i][2 * h + 1]) : "l"(a[i]), "l"(wp.y));
                }
            }
        }
        __syncthreads();
    }

    #pragma unroll
    for (int i = 0; i < 4; i++) {
        int row = base + ty + 32 * i;
        bool ok = (row < M);
        float d = 0.f;
        #pragma unroll
        for (int q = 0; q < QP; q++) {
            float2 v = *(float2*)&accv[i][q];
            int col = tx * CPT + 2 * q;
            if (!ok) continue;
            if (MODE == M_BIAS) {
                float2 b = *(const float2*)&b0[col];
                v.x += b.x; v.y += b.y;
            }
            if (MODE == M_COMB2) {
                float2 a2 = *(const float2*)&addsrc[(size_t)row * N + col];
                float2 a3 = *(const float2*)&addsrc2[(size_t)row * N + col];
                float2 ba = *(const float2*)&b0[col];
                float2 bb = *(const float2*)&b1[col];
                v.x = fmaxf(v.x + a2.x + a3.x + ba.x + bb.x, 0.f);
                v.y = fmaxf(v.y + a2.y + a3.y + ba.y + bb.y, 0.f);
            }
            if (MODE == M_SPLIT) {
                if (col < 64) {
                    *(float2*)&Y[(size_t)row * 64 + col] = v;
                } else {
                    int wc = col - 64;
                    *(float2*)&Y2[(size_t)row * 64 + wc] = v;
                    float2 w2 = *(const float2*)&av[wc];
                    d += v.x * w2.x + v.y * w2.y;
                }
            } else {
                *(float2*)&Y[(size_t)row * N + col] = v;
                if (MODE == M_DOT) {
                    float2 w2 = *(const float2*)&av[col];
                    d += v.x * w2.x + v.y * w2.y;
                }
            }
        }
        if (MODE == M_DOT || MODE == M_SPLIT) {
            #pragma unroll
            for (int o = 1; o < 8; o <<= 1) d += __shfl_xor_sync(0xFFFFFFFFu, d, o);
            if (tx == 0 && ok) dotout[row] = d;
        }
    }
}

// ---------------- host ----------------
static inline int cdiv(long long a, int b) { return (int)((a + b - 1) / b); }

extern "C" void kernel_launch(void* const* d_in, const int* in_sizes, int n_in,
                              void* d_out, int out_size) {
    const float* xp       = (const float*)d_in[0];
    const float* xa       = (const float*)d_in[1];
    const float* gcn_W0   = (const float*)d_in[2];
    const float* gcn_b0   = (const float*)d_in[3];
    const float* sage_Wl0 = (const float*)d_in[4];
    const float* sage_bl0 = (const float*)d_in[5];
    const float* sage_Wr0 = (const float*)d_in[6];
    const float* gat_Ws0  = (const float*)d_in[7];
    const float* gat_Wd0  = (const float*)d_in[8];
    const float* gat_as0  = (const float*)d_in[9];
    const float* gat_ad0  = (const float*)d_in[10];
    const float* gat_b0   = (const float*)d_in[11];
    const float* gat_Ws1  = (const float*)d_in[17];
    const float* gat_Wd1  = (const float*)d_in[18];
    const float* gat_as1  = (const float*)d_in[19];
    const float* gat_ad1  = (const float*)d_in[20];
    const float* gat_b1   = (const float*)d_in[21];
    const float* lin_W    = (const float*)d_in[22];
    const float* lin_b    = (const float*)d_in[23];
    const int* cs = (const int*)d_in[24];
    const int* cd = (const int*)d_in[25];
    const int* ws = (const int*)d_in[26];  // author idx of writes edge
    const int* wd = (const int*)d_in[27];  // paper idx of writes edge
    float* out = (float*)d_out;

    void* p;
    #define SYM(name) cudaGetSymbolAddress(&p, g_##name)
    SYM(xls);   float* xls  = (float*)p;
    SYM(P);     float* P    = (float*)p;
    SYM(G);     float* G    = (float*)p;
    SYM(SA);    float* SA   = (float*)p;
    SYM(XS);    float* XS   = (float*)p;
    SYM(XS1);   float* XS1  = (float*)p;
    SYM(XD);    float* XD   = (float*)p;
    SYM(xp1);   float* xp1  = (float*)p;
    SYM(xa1);   float* xa1  = (float*)p;
    SYM(Wcat);  float* Wcat = (float*)p;
    SYM(dis);   float* dis  = (float*)p;
    SYM(asrc);  float* asrc = (float*)p;
    SYM(adst);  float* adst = (float*)p;
    SYM(asrc1); float* asrc1 = (float*)p;
    SYM(adst1); float* adst1 = (float*)p;
    SYM(degC); int* degC = (int*)p;
    SYM(degWp); int* degWp = (int*)p;
    SYM(degWa); int* degWa = (int*)p;
    SYM(offC); int* offC = (int*)p;
    SYM(offWp); int* offWp = (int*)p;
    SYM(offWa); int* offWa = (int*)p;
    SYM(curC); int* curC = (int*)p;
    SYM(curWp); int* curWp = (int*)p;
    SYM(curWa); int* curWa = (int*)p;
    SYM(bsumA); int* bsumA = (int*)p;
    SYM(bsumB); int* bsumB = (int*)p;
    SYM(csrC); int* csrC = (int*)p;
    SYM(csrWp); int* csrWp = (int*)p;
    SYM(csrWa); int* csrWa = (int*)p;
    #undef SYM

    cudaFuncSetAttribute(k_gemm2<128, 64, M_PLAIN, 3>,
        cudaFuncAttributeMaxDynamicSharedMemorySize, gemm_smem_bytes<128, 64>());
    cudaFuncSetAttribute(k_gemm2<128, 128, M_SPLIT, 2>,
        cudaFuncAttributeMaxDynamicSharedMemorySize, gemm_smem_bytes<128, 128>());
    cudaFuncSetAttribute(k_gemm2<64, 64, M_DOT, 3>,
        cudaFuncAttributeMaxDynamicSharedMemorySize, gemm_smem_bytes<64, 64>());
    cudaFuncSetAttribute(k_gemm2<64, 64, M_COMB2, 3>,
        cudaFuncAttributeMaxDynamicSharedMemorySize, gemm_smem_bytes<64, 64>());
    cudaFuncSetAttribute(k_gemm2<64, 32, M_BIAS, 3>,
        cudaFuncAttributeMaxDynamicSharedMemorySize, gemm_smem_bytes<64, 32>());

    const int T = 256;
    cudaStream_t s0 = 0, sA, sB;
    cudaStreamCreateWithFlags(&sA, cudaStreamNonBlocking);
    cudaStreamCreateWithFlags(&sB, cudaStreamNonBlocking);
    cudaEvent_t eF, eXls, eG4, eSA, eGcn, eAuth;
    cudaEventCreateWithFlags(&eF,   cudaEventDisableTiming);
    cudaEventCreateWithFlags(&eXls, cudaEventDisableTiming);
    cudaEventCreateWithFlags(&eG4,  cudaEventDisableTiming);
    cudaEventCreateWithFlags(&eSA,  cudaEventDisableTiming);
    cudaEventCreateWithFlags(&eGcn, cudaEventDisableTiming);
    cudaEventCreateWithFlags(&eAuth, cudaEventDisableTiming);

    #define GEMM(Kk, Nn, MODE, MAXB, STRM, Xs, Ws_, B0, B1, ADD, ADD2, AV, DOT, Yy, Yy2, Mm) \
        k_gemm2<Kk, Nn, MODE, MAXB><<<cdiv(Mm, 128), 256, (gemm_smem_bytes<Kk, Nn>()), STRM>>>( \
            Xs, Ws_, B0, B1, ADD, ADD2, AV, DOT, Yy, Yy2, Mm)

    // ================= fork =================
    cudaEventRecord(eF, s0);
    cudaStreamWaitEvent(sA, eF, 0);
    cudaStreamWaitEvent(sB, eF, 0);

    // ---- s0: xls GEMM first (unblocks gcn_gather), then split P|XS GEMM ----
    GEMM(128, 64, M_PLAIN, 3, s0, xp, gcn_W0, nullptr, nullptr, nullptr, nullptr,
         nullptr, nullptr, xls, nullptr, NP);
    cudaEventRecord(eXls, s0);
    k_wcat2<<<cdiv(128 * 128, T), T, 0, s0>>>(sage_Wr0, gat_Ws0, Wcat);
    GEMM(128, 128, M_SPLIT, 2, s0, xp, Wcat, nullptr, nullptr, nullptr, nullptr,
         gat_as0, asrc, P, XS, NP);
    cudaEventRecord(eG4, s0);   // P + XS + asrc ready

    // ---- sA: cites CSR build, then gcn_gather (needs only xls + csrC) ----
    k_zero_i<<<cdiv(NP, T), T, 0, sA>>>(degC, NP);
    k_count<<<cdiv(EC, T), T, 0, sA>>>(cd, degC, EC);
    k_dis<<<cdiv(NP, T), T, 0, sA>>>(degC, dis, NP);
    k_scan1<<<cdiv(NP, 512), 512, 0, sA>>>(degC, offC, bsumA, NP);
    k_scan2<<<1, 512, 0, sA>>>(bsumA, cdiv(NP, 512));
    k_scan3<<<cdiv(NP, T), T, 0, sA>>>(offC, curC, bsumA, NP);
    k_fill<<<cdiv(EC, T), T, 0, sA>>>(cd, cs, curC, csrC, EC);
    cudaStreamWaitEvent(sA, eXls, 0);
    k_gcn_gather<<<cdiv((long long)NP * 32, T), T, 0, sA>>>(offC, csrC, xls, dis, G, NP, EC);
    cudaEventRecord(eGcn, sA);

    // ---- sB: XD0 GEMM first (needs only xa), then writes CSRs + sage + author ----
    GEMM(64, 64, M_DOT, 3, sB, xa, gat_Wd0, nullptr, nullptr, nullptr, nullptr,
         gat_ad0, adst, XD, nullptr, NA);
    k_zero_i<<<cdiv(NP, T), T, 0, sB>>>(degWp, NP);
    k_count<<<cdiv(EW, T), T, 0, sB>>>(wd, degWp, EW);
    k_scan1<<<cdiv(NP, 512), 512, 0, sB>>>(degWp, offWp, bsumB, NP);
    k_scan2<<<1, 512, 0, sB>>>(bsumB, cdiv(NP, 512));
    k_scan3<<<cdiv(NP, T), T, 0, sB>>>(offWp, curWp, bsumB, NP);
    k_fill<<<cdiv(EW, T), T, 0, sB>>>(wd, ws, curWp, csrWp, EW);
    k_sage_gather<<<cdiv((long long)NP * 32, T), T, 0, sB>>>(offWp, csrWp, xa, SA, NP, EW);
    cudaEventRecord(eSA, sB);
    k_zero_i<<<cdiv(NA, T), T, 0, sB>>>(degWa, NA);
    k_count<<<cdiv(EW, T), T, 0, sB>>>(ws, degWa, EW);
    k_scan1<<<cdiv(NA, 512), 512, 0, sB>>>(degWa, offWa, bsumB, NA);
    k_scan2<<<1, 512, 0, sB>>>(bsumB, cdiv(NA, 512));
    k_scan3<<<cdiv(NA, T), T, 0, sB>>>(offWa, curWa, bsumB, NA);
    k_fill<<<cdiv(EW, T), T, 0, sB>>>(ws, wd, curWa, csrWa, EW);
    cudaStreamWaitEvent(sB, eG4, 0);
    k_gat_gather<<<cdiv((long long)NA * 32, T), T, 0, sB>>>(offWa, csrWa, asrc, adst, XS,
                                                            gat_b0, xa1, NA, EW);
    GEMM(64, 64, M_DOT, 3, sB, xa1, gat_Wd1, nullptr, nullptr, nullptr, nullptr,
         gat_ad1, adst1, XD, nullptr, NA);
    cudaEventRecord(eAuth, sB);

    // ---- s0 (paper branch): comb2 + XS1, then final GAT + head ----
    cudaStreamWaitEvent(s0, eSA, 0);
    cudaStreamWaitEvent(s0, eGcn, 0);
    GEMM(64, 64, M_COMB2, 3, s0, SA, sage_Wl0, gcn_b0, sage_bl0, P, G,
         nullptr, nullptr, xp1, nullptr, NP);
    GEMM(64, 64, M_DOT, 3, s0, xp1, gat_Ws1, nullptr, nullptr, nullptr, nullptr,
         gat_as1, asrc1, XS1, nullptr, NP);
    cudaStreamWaitEvent(s0, eAuth, 0);
    k_gat_gather<<<cdiv((long long)NA * 32, T), T, 0, s0>>>(offWa, csrWa, asrc1, adst1, XS1,
                                                            gat_b1, xa1, NA, EW);
    GEMM(64, 32, M_BIAS, 3, s0, xa1, lin_W, lin_b, nullptr, nullptr, nullptr,
         nullptr, nullptr, out, nullptr, NA);
    #undef GEMM

    // destroy only outside capture
    cudaStreamCaptureStatus st = cudaStreamCaptureStatusNone;
    cudaStreamIsCapturing(sA, &st);
    if (st == cudaStreamCaptureStatusNone) {
        cudaEventDestroy(eF);  cudaEventDestroy(eXls); cudaEventDestroy(eG4);
        cudaEventDestroy(eSA); cudaEventDestroy(eGcn); cudaEventDestroy(eAuth);
        cudaStreamDestroy(sA); cudaStreamDestroy(sB);
    }
}

// round 14
// speedup vs baseline: 1.3446x; 1.3446x over previous
#include <cuda_runtime.h>
#include <cstdint>
#include <cstddef>

#define NP 200000
#define NA 100000
#define EC 4000000
#define EW 2000000

// ---------------- device scratch (allocation-free) ----------------
__device__ float g_xls[(size_t)NP * 64];   // raw x_paper @ gcn_W
__device__ float g_P  [(size_t)NP * 64];   // paper accumulation
__device__ float g_SA [(size_t)NP * 64];   // sage neighbor mean
__device__ float g_XS [(size_t)NP * 64];   // gat L0 source feats (paper)
__device__ float g_XS1[(size_t)NP * 64];   // gat L1 source feats (paper)
__device__ float g_XD [(size_t)NA * 64];   // gat dst feats (author)
__device__ float g_xp1[(size_t)NP * 64];   // x_paper after layer 0
__device__ float g_xa1[(size_t)NA * 64];   // x_author after layer 0/1
__device__ float g_Wcat[128 * 192];        // [gcn_W0 | sage_Wr0 | gat_Ws0]
__device__ float g_dis [NP];
__device__ float g_asrc[NP],  g_adst[NA];
__device__ float g_asrc1[NP], g_adst1[NA];
__device__ int g_degC[NP], g_degWp[NP], g_degWa[NA];
__device__ int g_offC[NP], g_offWp[NP], g_offWa[NA];
__device__ int g_curC[NP], g_curWp[NP], g_curWa[NA];
__device__ int g_bsumA[512], g_bsumB[512];
__device__ int g_csrC[EC], g_csrWp[EW], g_csrWa[EW];

// ---------------- utility kernels ----------------
__global__ void k_zero_i(int* p, int n) {
    int i = blockIdx.x * blockDim.x + threadIdx.x;
    if (i < n) p[i] = 0;
}
__global__ void k_count(const int* __restrict__ idx, int* cnt, int E) {
    int i = blockIdx.x * blockDim.x + threadIdx.x;
    if (i < E) atomicAdd(&cnt[idx[i]], 1);
}
__global__ void k_dis(const int* __restrict__ cnt, float* dis, int n) {
    int i = blockIdx.x * blockDim.x + threadIdx.x;
    if (i < n) dis[i] = rsqrtf((float)cnt[i] + 1.0f);
}
__global__ void k_wcat(const float* __restrict__ w0, const float* __restrict__ w1,
                       const float* __restrict__ w2, float* __restrict__ out) {
    int i = blockIdx.x * blockDim.x + threadIdx.x;
    if (i >= 128 * 192) return;
    int k = i / 192, c = i % 192;
    float v = (c < 64) ? w0[k * 64 + c]
            : (c < 128) ? w1[k * 64 + (c - 64)]
            : w2[k * 64 + (c - 128)];
    out[i] = v;
}

// ---------------- scan (3-phase, blocks of 512) ----------------
__global__ void k_scan1(const int* __restrict__ deg, int* off, int* bsum, int n) {
    __shared__ int sh[512];
    int t = threadIdx.x, i = blockIdx.x * 512 + t;
    int v = (i < n) ? deg[i] : 0;
    sh[t] = v; __syncthreads();
    #pragma unroll
    for (int o = 1; o < 512; o <<= 1) {
        int x = (t >= o) ? sh[t - o] : 0;
        __syncthreads(); sh[t] += x; __syncthreads();
    }
    if (i < n) off[i] = sh[t] - v;
    if (t == 511) bsum[blockIdx.x] = sh[511];
}
__global__ void k_scan2(int* bsum, int nb) {
    __shared__ int sh[512];
    int t = threadIdx.x;
    int v = (t < nb) ? bsum[t] : 0;
    sh[t] = v; __syncthreads();
    #pragma unroll
    for (int o = 1; o < 512; o <<= 1) {
        int x = (t >= o) ? sh[t - o] : 0;
        __syncthreads(); sh[t] += x; __syncthreads();
    }
    if (t < nb) bsum[t] = sh[t] - v;
}
__global__ void k_scan3(int* off, int* cur, const int* __restrict__ bsum, int n) {
    int i = blockIdx.x * blockDim.x + threadIdx.x;
    if (i < n) { int v = off[i] + bsum[i >> 9]; off[i] = v; cur[i] = v; }
}
__global__ void k_fill(const int* __restrict__ dst, const int* __restrict__ src,
                       int* cur, int* csr, int E) {
    int i = blockIdx.x * blockDim.x + threadIdx.x;
    if (i < E) {
        int pos = atomicAdd(&cur[dst[i]], 1);
        csr[pos] = src[i];
    }
}

// ---------------- gathers (1 warp / node, 2 cols / lane) ----------------
__global__ void k_gcn_gather(const int* __restrict__ off, const int* __restrict__ csr,
                             const float* __restrict__ xls, const float* __restrict__ dis,
                             float* __restrict__ P, int n, int E) {
    int w = (blockIdx.x * blockDim.x + threadIdx.x) >> 5;
    int lane = threadIdx.x & 31;
    if (w >= n) return;
    int beg = off[w], end = (w == n - 1) ? E : off[w + 1];
    float a0 = 0.f, a1 = 0.f;
    int t = beg;
    for (; t + 4 <= end; t += 4) {
        int s0 = __ldg(&csr[t]),     s1 = __ldg(&csr[t + 1]);
        int s2 = __ldg(&csr[t + 2]), s3 = __ldg(&csr[t + 3]);
        float d0 = __ldg(&dis[s0]), d1 = __ldg(&dis[s1]);
        float d2 = __ldg(&dis[s2]), d3 = __ldg(&dis[s3]);
        float b0 = xls[s0 * 64 + lane],      c0 = xls[s0 * 64 + 32 + lane];
        float b1 = xls[s1 * 64 + lane],      c1 = xls[s1 * 64 + 32 + lane];
        float b2 = xls[s2 * 64 + lane],      c2 = xls[s2 * 64 + 32 + lane];
        float b3 = xls[s3 * 64 + lane],      c3 = xls[s3 * 64 + 32 + lane];
        a0 += (d0 * b0 + d1 * b1) + (d2 * b2 + d3 * b3);
        a1 += (d0 * c0 + d1 * c1) + (d2 * c2 + d3 * c3);
    }
    for (; t < end; t++) {
        int s = __ldg(&csr[t]);
        float d = __ldg(&dis[s]);
        a0 += d * xls[s * 64 + lane];
        a1 += d * xls[s * 64 + 32 + lane];
    }
    float dd = dis[w];
    P[(size_t)w * 64 + lane]      += dd * (a0 + dd * xls[w * 64 + lane]);
    P[(size_t)w * 64 + 32 + lane] += dd * (a1 + dd * xls[w * 64 + 32 + lane]);
}

__global__ void k_sage_gather(const int* __restrict__ off, const int* __restrict__ csr,
                              const float* __restrict__ xa, float* __restrict__ SA,
                              int n, int E) {
    int w = (blockIdx.x * blockDim.x + threadIdx.x) >> 5;
    int lane = threadIdx.x & 31;
    if (w >= n) return;
    int beg = off[w], end = (w == n - 1) ? E : off[w + 1];
    float a0 = 0.f, a1 = 0.f;
    int t = beg;
    for (; t + 4 <= end; t += 4) {
        int s0 = __ldg(&csr[t]),     s1 = __ldg(&csr[t + 1]);
        int s2 = __ldg(&csr[t + 2]), s3 = __ldg(&csr[t + 3]);
        float b0 = xa[s0 * 64 + lane],      c0 = xa[s0 * 64 + 32 + lane];
        float b1 = xa[s1 * 64 + lane],      c1 = xa[s1 * 64 + 32 + lane];
        float b2 = xa[s2 * 64 + lane],      c2 = xa[s2 * 64 + 32 + lane];
        float b3 = xa[s3 * 64 + lane],      c3 = xa[s3 * 64 + 32 + lane];
        a0 += (b0 + b1) + (b2 + b3);
        a1 += (c0 + c1) + (c2 + c3);
    }
    for (; t < end; t++) {
        int s = __ldg(&csr[t]);
        a0 += xa[s * 64 + lane];
        a1 += xa[s * 64 + 32 + lane];
    }
    float r = 1.0f / fmaxf((float)(end - beg), 1.0f);
    SA[(size_t)w * 64 + lane]      = a0 * r;
    SA[(size_t)w * 64 + 32 + lane] = a1 * r;
}

__global__ void k_gat_gather(const int* __restrict__ off, const int* __restrict__ csr,
                             const float* __restrict__ asrc, const float* __restrict__ adst,
                             const float* __restrict__ XS, const float* __restrict__ bias,
                             float* __restrict__ out, int n, int E) {
    int w = (blockIdx.x * blockDim.x + threadIdx.x) >> 5;
    int lane = threadIdx.x & 31;
    if (w >= n) return;
    int beg = off[w], end = (w == n - 1) ? E : off[w + 1];
    float ad = adst[w];
    float den = 0.f, a0 = 0.f, a1 = 0.f;
    int t = beg;
    for (; t + 4 <= end; t += 4) {
        int p0 = __ldg(&csr[t]),     p1 = __ldg(&csr[t + 1]);
        int p2 = __ldg(&csr[t + 2]), p3 = __ldg(&csr[t + 3]);
        float e0 = asrc[p0] + ad; e0 = (e0 > 0.f) ? e0 : 0.2f * e0;
        float e1 = asrc[p1] + ad; e1 = (e1 > 0.f) ? e1 : 0.2f * e1;
        float e2 = asrc[p2] + ad; e2 = (e2 > 0.f) ? e2 : 0.2f * e2;
        float e3 = asrc[p3] + ad; e3 = (e3 > 0.f) ? e3 : 0.2f * e3;
        float x0 = __expf(e0), x1 = __expf(e1), x2 = __expf(e2), x3 = __expf(e3);
        float b0 = XS[p0 * 64 + lane],      c0 = XS[p0 * 64 + 32 + lane];
        float b1 = XS[p1 * 64 + lane],      c1 = XS[p1 * 64 + 32 + lane];
        float b2 = XS[p2 * 64 + lane],      c2 = XS[p2 * 64 + 32 + lane];
        float b3 = XS[p3 * 64 + lane],      c3 = XS[p3 * 64 + 32 + lane];
        den += (x0 + x1) + (x2 + x3);
        a0 += (x0 * b0 + x1 * b1) + (x2 * b2 + x3 * b3);
        a1 += (x0 * c0 + x1 * c1) + (x2 * c2 + x3 * c3);
    }
    for (; t < end; t++) {
        int p = __ldg(&csr[t]);
        float e = asrc[p] + ad; e = (e > 0.f) ? e : 0.2f * e;
        float x = __expf(e);
        den += x;
        a0 += x * XS[p * 64 + lane];
        a1 += x * XS[p * 64 + 32 + lane];
    }
    float r = (den > 0.f) ? (1.0f / den) : 0.f;
    float o0 = a0 * r + bias[lane];
    float o1 = a1 * r + bias[lane + 32];
    out[(size_t)w * 64 + lane]      = fmaxf(o0, 0.f);
    out[(size_t)w * 64 + 32 + lane] = fmaxf(o1, 0.f);
}

// ---------------- cp.async double-buffered f32x2 GEMM (proven R10) ----------------
#define M_PLAIN 0
#define M_COMB  2
#define M_DOT   3
#define M_BIAS  4
#define XSTR 36
#define XSZ  (128 * XSTR)

template <int K, int N>
constexpr int gemm_smem_bytes() { return (2 * XSZ + 2 * 32 * N) * 4; }

template <int K, int N, int MODE>
__global__ void __launch_bounds__(256, 3) k_gemm2(
        const float* __restrict__ X, const float* __restrict__ W,
        const float* __restrict__ b0, const float* __restrict__ b1,
        const float* __restrict__ addsrc,
        const float* __restrict__ av, float* __restrict__ dotout,
        float* __restrict__ Y, int M) {
    constexpr int CPT = N / 8;
    constexpr int QP  = CPT / 2;
    constexpr int NCH = K / 32;
    extern __shared__ __align__(16) float smemf[];
    float* Xsb[2] = { smemf, smemf + XSZ };
    float* Wsb[2] = { smemf + 2 * XSZ, smemf + 2 * XSZ + 32 * N };
    unsigned xs_u32[2], ws_u32[2];
    xs_u32[0] = (unsigned)__cvta_generic_to_shared(Xsb[0]);
    xs_u32[1] = (unsigned)__cvta_generic_to_shared(Xsb[1]);
    ws_u32[0] = (unsigned)__cvta_generic_to_shared(Wsb[0]);
    ws_u32[1] = (unsigned)__cvta_generic_to_shared(Wsb[1]);

    int tid = threadIdx.x;
    int tx = tid & 7, ty = tid >> 3;
    int base = blockIdx.x * 128;

    auto stage = [&](int c, int b) {
        int kc = c * 32;
        #pragma unroll
        for (int j = 0; j < 4; j++) {
            int v = tid + j * 256;
            int r = v >> 3;
            int k0 = (v & 7) * 4;
            int rr = base + r;
            const float* src = X + (size_t)(rr < M ? rr : 0) * K + kc + k0;
            unsigned ssize = (rr < M) ? 16u : 0u;
            unsigned daddr = xs_u32[b] + (unsigned)(r * XSTR + k0) * 4u;
            asm volatile("cp.async.cg.shared.global [%0], [%1], 16, %2;"
                         :: "r"(daddr), "l"(src), "r"(ssize));
        }
        #pragma unroll
        for (int j = 0; j < N / 32; j++) {
            int v = tid + j * 256;
            int r = (v * 4) / N;
            int cc = (v * 4) % N;
            const float* src = W + (size_t)(kc + r) * N + cc;
            unsigned daddr = ws_u32[b] + (unsigned)(r * N + cc) * 4u;
            asm volatile("cp.async.cg.shared.global [%0], [%1], 16;"
                         :: "r"(daddr), "l"(src));
        }
    };

    unsigned long long accv[4][QP];
    #pragma unroll
    for (int i = 0; i < 4; i++)
        #pragma unroll
        for (int q = 0; q < QP; q++) accv[i][q] = 0ull;

    stage(0, 0);
    asm volatile("cp.async.commit_group;");

    for (int c = 0; c < NCH; c++) {
        int buf = c & 1;
        if (c + 1 < NCH) {
            stage(c + 1, (c + 1) & 1);
            asm volatile("cp.async.commit_group;");
            asm volatile("cp.async.wait_group 1;");
        } else {
            asm volatile("cp.async.wait_group 0;");
        }
        __syncthreads();
        const float* Xc = Xsb[buf];
        const float* Wc = Wsb[buf];
        #pragma unroll
        for (int k = 0; k < 32; k++) {
            unsigned long long a[4];
            #pragma unroll
            for (int i = 0; i < 4; i++) {
                unsigned a32 = *(const unsigned*)&Xc[(ty + 32 * i) * XSTR + k];
                asm("mov.b64 %0, {%1, %1};" : "=l"(a[i]) : "r"(a32));
            }
            #pragma unroll
            for (int h = 0; h < QP / 2; h++) {
                ulonglong2 wp = *(const ulonglong2*)&Wc[k * N + tx * CPT + h * 4];
                #pragma unroll
                for (int i = 0; i < 4; i++) {
                    asm("fma.rn.f32x2 %0, %1, %2, %0;"
                        : "+l"(accv[i][2 * h]) : "l"(a[i]), "l"(wp.x));
                    asm("fma.rn.f32x2 %0, %1, %2, %0;"
                        : "+l"(accv[i][2 * h + 1]) : "l"(a[i]), "l"(wp.y));
                }
            }
        }
        __syncthreads();
    }

    #pragma unroll
    for (int i = 0; i < 4; i++) {
        int row = base + ty + 32 * i;
        if (row >= M) continue;
        float d = 0.f;
        #pragma unroll
        for (int q = 0; q < QP; q++) {
            float2 v = *(float2*)&accv[i][q];
            int col = tx * CPT + 2 * q;
            if (MODE == M_BIAS) {
                float2 b = *(const float2*)&b0[col];
                v.x += b.x; v.y += b.y;
            }
            if (MODE == M_COMB) {
                float2 a2 = *(const float2*)&addsrc[(size_t)row * N + col];
                float2 ba = *(const float2*)&b0[col];
                float2 bb = *(const float2*)&b1[col];
                v.x = fmaxf(v.x + a2.x + ba.x + bb.x, 0.f);
                v.y = fmaxf(v.y + a2.y + ba.y + bb.y, 0.f);
            }
            *(float2*)&Y[(size_t)row * N + col] = v;
            if (MODE == M_DOT) {
                float2 w2 = *(const float2*)&av[col];
                d += v.x * w2.x + v.y * w2.y;
            }
        }
        if (MODE == M_DOT) {
            #pragma unroll
            for (int o = 1; o < 8; o <<= 1) d += __shfl_xor_sync(0xFFFFFFFFu, d, o);
            if (tx == 0) dotout[row] = d;
        }
    }
}

// ---------------- fused layer-0 paper GEMM: K=128, N=192, 3 outputs ----------------
#define FK 128
#define FN 192
#define FXSZ (64 * XSTR)
#define FWSZ (32 * FN)
constexpr int gemmF_smem_bytes() { return (2 * FXSZ + 2 * FWSZ) * 4; }

__global__ void __launch_bounds__(256, 2) k_gemmF(
        const float* __restrict__ X, const float* __restrict__ W,
        const float* __restrict__ av, float* __restrict__ dotout,
        float* __restrict__ Y0, float* __restrict__ Y1, float* __restrict__ Y2,
        int M) {
    extern __shared__ __align__(16) float smemf[];
    float* Xsb[2] = { smemf, smemf + FXSZ };
    float* Wsb[2] = { smemf + 2 * FXSZ, smemf + 2 * FXSZ + FWSZ };
    unsigned xs_u32[2], ws_u32[2];
    xs_u32[0] = (unsigned)__cvta_generic_to_shared(Xsb[0]);
    xs_u32[1] = (unsigned)__cvta_generic_to_shared(Xsb[1]);
    ws_u32[0] = (unsigned)__cvta_generic_to_shared(Wsb[0]);
    ws_u32[1] = (unsigned)__cvta_generic_to_shared(Wsb[1]);

    int tid = threadIdx.x;
    int tx = tid & 15, ty = tid >> 4;
    int base = blockIdx.x * 64;

    auto stage = [&](int c, int b) {
        int kc = c * 32;
        #pragma unroll
        for (int j = 0; j < 2; j++) {
            int v = tid + j * 256;
            int r = v >> 3;
            int k0 = (v & 7) * 4;
            int rr = base + r;
            const float* src = X + (size_t)(rr < M ? rr : 0) * FK + kc + k0;
            unsigned ssize = (rr < M) ? 16u : 0u;
            unsigned daddr = xs_u32[b] + (unsigned)(r * XSTR + k0) * 4u;
            asm volatile("cp.async.cg.shared.global [%0], [%1], 16, %2;"
                         :: "r"(daddr), "l"(src), "r"(ssize));
        }
        #pragma unroll
        for (int j = 0; j < 6; j++) {
            int v = tid + j * 256;
            int r = v / 48;
            int cc = (v % 48) * 4;
            const float* src = W + (size_t)(kc + r) * FN + cc;
            unsigned daddr = ws_u32[b] + (unsigned)(r * FN + cc) * 4u;
            asm volatile("cp.async.cg.shared.global [%0], [%1], 16;"
                         :: "r"(daddr), "l"(src));
        }
    };

    unsigned long long accv[4][6];
    #pragma unroll
    for (int i = 0; i < 4; i++)
        #pragma unroll
        for (int q = 0; q < 6; q++) accv[i][q] = 0ull;

    stage(0, 0);
    asm volatile("cp.async.commit_group;");

    for (int c = 0; c < FK / 32; c++) {
        int buf = c & 1;
        if (c + 1 < FK / 32) {
            stage(c + 1, (c + 1) & 1);
            asm volatile("cp.async.commit_group;");
            asm volatile("cp.async.wait_group 1;");
        } else {
            asm volatile("cp.async.wait_group 0;");
        }
        __syncthreads();
        const float* Xc = Xsb[buf];
        const float* Wc = Wsb[buf];
        #pragma unroll
        for (int kk = 0; kk < 16; kk++) {
            int k = kk * 2;
            float2 ap[4];
            #pragma unroll
            for (int i = 0; i < 4; i++)
                ap[i] = *(const float2*)&Xc[(ty + 16 * i) * XSTR + k];
            #pragma unroll
            for (int s = 0; s < 2; s++) {
                unsigned long long a[4];
                #pragma unroll
                for (int i = 0; i < 4; i++) {
                    unsigned a32 = __float_as_uint(s ? ap[i].y : ap[i].x);
                    asm("mov.b64 %0, {%1, %1};" : "=l"(a[i]) : "r"(a32));
                }
                const float* wrow = &Wc[(k + s) * FN + tx * 12];
                ulonglong2 p0 = *(const ulonglong2*)(wrow);
                ulonglong2 p1 = *(const ulonglong2*)(wrow + 4);
                ulonglong2 p2 = *(const ulonglong2*)(wrow + 8);
                #pragma unroll
                for (int i = 0; i < 4; i++) {
                    asm("fma.rn.f32x2 %0, %1, %2, %0;" : "+l"(accv[i][0]) : "l"(a[i]), "l"(p0.x));
                    asm("fma.rn.f32x2 %0, %1, %2, %0;" : "+l"(accv[i][1]) : "l"(a[i]), "l"(p0.y));
                    asm("fma.rn.f32x2 %0, %1, %2, %0;" : "+l"(accv[i][2]) : "l"(a[i]), "l"(p1.x));
                    asm("fma.rn.f32x2 %0, %1, %2, %0;" : "+l"(accv[i][3]) : "l"(a[i]), "l"(p1.y));
                    asm("fma.rn.f32x2 %0, %1, %2, %0;" : "+l"(accv[i][4]) : "l"(a[i]), "l"(p2.x));
                    asm("fma.rn.f32x2 %0, %1, %2, %0;" : "+l"(accv[i][5]) : "l"(a[i]), "l"(p2.y));
                }
            }
        }
        __syncthreads();
    }

    #pragma unroll
    for (int i = 0; i < 4; i++) {
        int row = base + ty + 16 * i;
        bool ok = (row < M);
        float d = 0.f;
        #pragma unroll
        for (int q = 0; q < 6; q++) {
            float2 v = *(float2*)&accv[i][q];
            int col = tx * 12 + 2 * q;
            int sec = col >> 6;
            int within = col & 63;
            if (ok) {
                float* dst = (sec == 0) ? Y0 : ((sec == 1) ? Y1 : Y2);
                *(float2*)&dst[(size_t)row * 64 + within] = v;
                if (sec == 2) {
                    float2 w2 = *(const float2*)&av[within];
                    d += v.x * w2.x + v.y * w2.y;
                }
            }
        }
        #pragma unroll
        for (int o = 1; o < 16; o <<= 1) d += __shfl_xor_sync(0xFFFFFFFFu, d, o);
        if (tx == 0 && ok) dotout[row] = d;
    }
}

// ---------------- host ----------------
static inline int cdiv(long long a, int b) { return (int)((a + b - 1) / b); }

extern "C" void kernel_launch(void* const* d_in, const int* in_sizes, int n_in,
                              void* d_out, int out_size) {
    const float* xp       = (const float*)d_in[0];
    const float* xa       = (const float*)d_in[1];
    const float* gcn_W0   = (const float*)d_in[2];
    const float* gcn_b0   = (const float*)d_in[3];
    const float* sage_Wl0 = (const float*)d_in[4];
    const float* sage_bl0 = (const float*)d_in[5];
    const float* sage_Wr0 = (const float*)d_in[6];
    const float* gat_Ws0  = (const float*)d_in[7];
    const float* gat_Wd0  = (const float*)d_in[8];
    const float* gat_as0  = (const float*)d_in[9];
    const float* gat_ad0  = (const float*)d_in[10];
    const float* gat_b0   = (const float*)d_in[11];
    const float* gat_Ws1  = (const float*)d_in[17];
    const float* gat_Wd1  = (const float*)d_in[18];
    const float* gat_as1  = (const float*)d_in[19];
    const float* gat_ad1  = (const float*)d_in[20];
    const float* gat_b1   = (const float*)d_in[21];
    const float* lin_W    = (const float*)d_in[22];
    const float* lin_b    = (const float*)d_in[23];
    const int* cs = (const int*)d_in[24];
    const int* cd = (const int*)d_in[25];
    const int* ws = (const int*)d_in[26];  // author idx of writes edge
    const int* wd = (const int*)d_in[27];  // paper idx of writes edge
    float* out = (float*)d_out;

    void* p;
    #define SYM(name) cudaGetSymbolAddress(&p, g_##name)
    SYM(xls);   float* xls  = (float*)p;
    SYM(P);     float* P    = (float*)p;
    SYM(SA);    float* SA   = (float*)p;
    SYM(XS);    float* XS   = (float*)p;
    SYM(XS1);   float* XS1  = (float*)p;
    SYM(XD);    float* XD   = (float*)p;
    SYM(xp1);   float* xp1  = (float*)p;
    SYM(xa1);   float* xa1  = (float*)p;
    SYM(Wcat);  float* Wcat = (float*)p;
    SYM(dis);   float* dis  = (float*)p;
    SYM(asrc);  float* asrc = (float*)p;
    SYM(adst);  float* adst = (float*)p;
    SYM(asrc1); float* asrc1 = (float*)p;
    SYM(adst1); float* adst1 = (float*)p;
    SYM(degC); int* degC = (int*)p;
    SYM(degWp); int* degWp = (int*)p;
    SYM(degWa); int* degWa = (int*)p;
    SYM(offC); int* offC = (int*)p;
    SYM(offWp); int* offWp = (int*)p;
    SYM(offWa); int* offWa = (int*)p;
    SYM(curC); int* curC = (int*)p;
    SYM(curWp); int* curWp = (int*)p;
    SYM(curWa); int* curWa = (int*)p;
    SYM(bsumA); int* bsumA = (int*)p;
    SYM(bsumB); int* bsumB = (int*)p;
    SYM(csrC); int* csrC = (int*)p;
    SYM(csrWp); int* csrWp = (int*)p;
    SYM(csrWa); int* csrWa = (int*)p;
    #undef SYM

    cudaFuncSetAttribute(k_gemmF,
        cudaFuncAttributeMaxDynamicSharedMemorySize, gemmF_smem_bytes());
    cudaFuncSetAttribute(k_gemm2<64, 64, M_DOT>,
        cudaFuncAttributeMaxDynamicSharedMemorySize, gemm_smem_bytes<64, 64>());
    cudaFuncSetAttribute(k_gemm2<64, 64, M_COMB>,
        cudaFuncAttributeMaxDynamicSharedMemorySize, gemm_smem_bytes<64, 64>());
    cudaFuncSetAttribute(k_gemm2<64, 32, M_BIAS>,
        cudaFuncAttributeMaxDynamicSharedMemorySize, gemm_smem_bytes<64, 32>());

    const int T = 256;
    cudaStream_t s0 = 0, sA, sB;
    cudaStreamCreateWithFlags(&sA, cudaStreamNonBlocking);
    cudaStreamCreateWithFlags(&sB, cudaStreamNonBlocking);
    cudaEvent_t eF, eG2, eSA, eGcn, eAuth;
    cudaEventCreateWithFlags(&eF,   cudaEventDisableTiming);
    cudaEventCreateWithFlags(&eG2,  cudaEventDisableTiming);
    cudaEventCreateWithFlags(&eSA,  cudaEventDisableTiming);
    cudaEventCreateWithFlags(&eGcn, cudaEventDisableTiming);
    cudaEventCreateWithFlags(&eAuth, cudaEventDisableTiming);

    #define GEMM(Kk, Nn, MODE, STRM, Xs, Ws_, B0, B1, ADD, AV, DOT, Yy, Mm) \
        k_gemm2<Kk, Nn, MODE><<<cdiv(Mm, 128), 256, (gemm_smem_bytes<Kk, Nn>()), STRM>>>( \
            Xs, Ws_, B0, B1, ADD, AV, DOT, Yy, Mm)

    // ================= fork =================
    cudaEventRecord(eF, s0);
    cudaStreamWaitEvent(sA, eF, 0);
    cudaStreamWaitEvent(sB, eF, 0);

    // ---- s0: fused layer-0 paper GEMM (gcn|sageWr|gatWs + asrc dot) ----
    k_wcat<<<cdiv(128 * 192, T), T, 0, s0>>>(gcn_W0, sage_Wr0, gat_Ws0, Wcat);
    k_gemmF<<<cdiv(NP, 64), 256, gemmF_smem_bytes(), s0>>>(
        xp, Wcat, gat_as0, asrc, xls, P, XS, NP);
    cudaEventRecord(eG2, s0);   // xls + P + XS + asrc ready

    // ---- sA: cites CSR build, then gcn_gather as soon as xls+P ready ----
    k_zero_i<<<cdiv(NP, T), T, 0, sA>>>(degC, NP);
    k_count<<<cdiv(EC, T), T, 0, sA>>>(cd, degC, EC);
    k_dis<<<cdiv(NP, T), T, 0, sA>>>(degC, dis, NP);
    k_scan1<<<cdiv(NP, 512), 512, 0, sA>>>(degC, offC, bsumA, NP);
    k_scan2<<<1, 512, 0, sA>>>(bsumA, cdiv(NP, 512));
    k_scan3<<<cdiv(NP, T), T, 0, sA>>>(offC, curC, bsumA, NP);
    k_fill<<<cdiv(EC, T), T, 0, sA>>>(cd, cs, curC, csrC, EC);
    cudaStreamWaitEvent(sA, eG2, 0);
    k_gcn_gather<<<cdiv((long long)NP * 32, T), T, 0, sA>>>(offC, csrC, xls, dis, P, NP, EC);
    cudaEventRecord(eGcn, sA);

    // ---- sB: XD0 GEMM first (needs only xa -> overlaps gemmF), then CSRs etc. ----
    GEMM(64, 64, M_DOT, sB, xa, gat_Wd0, nullptr, nullptr, nullptr, gat_ad0, adst, XD, NA);
    k_zero_i<<<cdiv(NP, T), T, 0, sB>>>(degWp, NP);
    k_count<<<cdiv(EW, T), T, 0, sB>>>(wd, degWp, EW);
    k_scan1<<<cdiv(NP, 512), 512, 0, sB>>>(degWp, offWp, bsumB, NP);
    k_scan2<<<1, 512, 0, sB>>>(bsumB, cdiv(NP, 512));
    k_scan3<<<cdiv(NP, T), T, 0, sB>>>(offWp, curWp, bsumB, NP);
    k_fill<<<cdiv(EW, T), T, 0, sB>>>(wd, ws, curWp, csrWp, EW);
    k_sage_gather<<<cdiv((long long)NP * 32, T), T, 0, sB>>>(offWp, csrWp, xa, SA, NP, EW);
    cudaEventRecord(eSA, sB);
    k_zero_i<<<cdiv(NA, T), T, 0, sB>>>(degWa, NA);
    k_count<<<cdiv(EW, T), T, 0, sB>>>(ws, degWa, EW);
    k_scan1<<<cdiv(NA, 512), 512, 0, sB>>>(degWa, offWa, bsumB, NA);
    k_scan2<<<1, 512, 0, sB>>>(bsumB, cdiv(NA, 512));
    k_scan3<<<cdiv(NA, T), T, 0, sB>>>(offWa, curWa, bsumB, NA);
    k_fill<<<cdiv(EW, T), T, 0, sB>>>(ws, wd, curWa, csrWa, EW);
    // gat L0 gather needs XS/asrc from gemmF (eG2); adst already local to sB
    cudaStreamWaitEvent(sB, eG2, 0);
    k_gat_gather<<<cdiv((long long)NA * 32, T), T, 0, sB>>>(offWa, csrWa, asrc, adst, XS,
                                                            gat_b0, xa1, NA, EW);
    GEMM(64, 64, M_DOT, sB, xa1, gat_Wd1, nullptr, nullptr, nullptr, gat_ad1, adst1, XD, NA);
    cudaEventRecord(eAuth, sB);

    // ---- s0 (paper branch): comb + XS1, then final GAT + head ----
    cudaStreamWaitEvent(s0, eSA, 0);
    cudaStreamWaitEvent(s0, eGcn, 0);
    GEMM(64, 64, M_COMB, s0, SA, sage_Wl0, gcn_b0, sage_bl0, P, nullptr, nullptr, xp1, NP);
    GEMM(64, 64, M_DOT,  s0, xp1, gat_Ws1, nullptr, nullptr, nullptr, gat_as1, asrc1, XS1, NP);
    cudaStreamWaitEvent(s0, eAuth, 0);
    k_gat_gather<<<cdiv((long long)NA * 32, T), T, 0, s0>>>(offWa, csrWa, asrc1, adst1, XS1,
                                                            gat_b1, xa1, NA, EW);
    GEMM(64, 32, M_BIAS, s0, xa1, lin_W, lin_b, nullptr, nullptr, nullptr, nullptr, out, NA);
    #undef GEMM

    // destroy only outside capture
    cudaStreamCaptureStatus st = cudaStreamCaptureStatusNone;
    cudaStreamIsCapturing(sA, &st);
    if (st == cudaStreamCaptureStatusNone) {
        cudaEventDestroy(eF);  cudaEventDestroy(eG2);
        cudaEventDestroy(eSA); cudaEventDestroy(eGcn); cudaEventDestroy(eAuth);
        cudaStreamDestroy(sA); cudaStreamDestroy(sB);
    }
}

// round 15
// speedup vs baseline: 1.3678x; 1.0172x over previous
#include <cuda_runtime.h>
#include <cstdint>
#include <cstddef>

#define NP 200000
#define NA 100000
#define EC 4000000
#define EW 2000000

// ---------------- device scratch (allocation-free) ----------------
__device__ float g_xls[(size_t)NP * 64];   // raw x_paper @ gcn_W
__device__ float g_P  [(size_t)NP * 64];   // paper accumulation
__device__ float g_SA [(size_t)NP * 64];   // sage neighbor mean
__device__ float g_XS [(size_t)NP * 64];   // gat L0 source feats (paper)
__device__ float g_XS1[(size_t)NP * 64];   // gat L1 source feats (paper)
__device__ float g_XD [(size_t)NA * 64];   // gat dst feats (author)
__device__ float g_xa1[(size_t)NA * 64];   // x_author after layer 0/1
__device__ float g_Wcat[128 * 192];        // [gcn_W0 | sage_Wr0 | gat_Ws0]
__device__ float g_dis [NP];
__device__ float g_asrc[NP],  g_adst[NA];
__device__ float g_asrc1[NP], g_adst1[NA];
__device__ int g_degC[NP], g_degWp[NP], g_degWa[NA];
__device__ int g_offC[NP], g_offWp[NP], g_offWa[NA];
__device__ int g_curC[NP], g_curWp[NP], g_curWa[NA];
__device__ int g_bsumA[512], g_bsumB[512];
__device__ int g_csrC[EC], g_csrWp[EW], g_csrWa[EW];

// ---------------- utility kernels ----------------
__global__ void k_zero_i(int* p, int n) {
    int i = blockIdx.x * blockDim.x + threadIdx.x;
    if (i < n) p[i] = 0;
}
__global__ void k_count(const int* __restrict__ idx, int* cnt, int E) {
    int i = blockIdx.x * blockDim.x + threadIdx.x;
    if (i < E) atomicAdd(&cnt[idx[i]], 1);
}
__global__ void k_dis(const int* __restrict__ cnt, float* dis, int n) {
    int i = blockIdx.x * blockDim.x + threadIdx.x;
    if (i < n) dis[i] = rsqrtf((float)cnt[i] + 1.0f);
}
__global__ void k_wcat(const float* __restrict__ w0, const float* __restrict__ w1,
                       const float* __restrict__ w2, float* __restrict__ out) {
    int i = blockIdx.x * blockDim.x + threadIdx.x;
    if (i >= 128 * 192) return;
    int k = i / 192, c = i % 192;
    float v = (c < 64) ? w0[k * 64 + c]
            : (c < 128) ? w1[k * 64 + (c - 64)]
            : w2[k * 64 + (c - 128)];
    out[i] = v;
}

// ---------------- scan (3-phase, blocks of 512) ----------------
__global__ void k_scan1(const int* __restrict__ deg, int* off, int* bsum, int n) {
    __shared__ int sh[512];
    int t = threadIdx.x, i = blockIdx.x * 512 + t;
    int v = (i < n) ? deg[i] : 0;
    sh[t] = v; __syncthreads();
    #pragma unroll
    for (int o = 1; o < 512; o <<= 1) {
        int x = (t >= o) ? sh[t - o] : 0;
        __syncthreads(); sh[t] += x; __syncthreads();
    }
    if (i < n) off[i] = sh[t] - v;
    if (t == 511) bsum[blockIdx.x] = sh[511];
}
__global__ void k_scan2(int* bsum, int nb) {
    __shared__ int sh[512];
    int t = threadIdx.x;
    int v = (t < nb) ? bsum[t] : 0;
    sh[t] = v; __syncthreads();
    #pragma unroll
    for (int o = 1; o < 512; o <<= 1) {
        int x = (t >= o) ? sh[t - o] : 0;
        __syncthreads(); sh[t] += x; __syncthreads();
    }
    if (t < nb) bsum[t] = sh[t] - v;
}
__global__ void k_scan3(int* off, int* cur, const int* __restrict__ bsum, int n) {
    int i = blockIdx.x * blockDim.x + threadIdx.x;
    if (i < n) { int v = off[i] + bsum[i >> 9]; off[i] = v; cur[i] = v; }
}
__global__ void k_fill(const int* __restrict__ dst, const int* __restrict__ src,
                       int* cur, int* csr, int E) {
    int i = blockIdx.x * blockDim.x + threadIdx.x;
    if (i < E) {
        int pos = atomicAdd(&cur[dst[i]], 1);
        csr[pos] = src[i];
    }
}

// ---------------- gathers (1 warp / node, 2 cols / lane) ----------------
__global__ void k_gcn_gather(const int* __restrict__ off, const int* __restrict__ csr,
                             const float* __restrict__ xls, const float* __restrict__ dis,
                             float* __restrict__ P, int n, int E) {
    int w = (blockIdx.x * blockDim.x + threadIdx.x) >> 5;
    int lane = threadIdx.x & 31;
    if (w >= n) return;
    int beg = off[w], end = (w == n - 1) ? E : off[w + 1];
    float a0 = 0.f, a1 = 0.f;
    int t = beg;
    for (; t + 4 <= end; t += 4) {
        int s0 = __ldg(&csr[t]),     s1 = __ldg(&csr[t + 1]);
        int s2 = __ldg(&csr[t + 2]), s3 = __ldg(&csr[t + 3]);
        float d0 = __ldg(&dis[s0]), d1 = __ldg(&dis[s1]);
        float d2 = __ldg(&dis[s2]), d3 = __ldg(&dis[s3]);
        float b0 = xls[s0 * 64 + lane],      c0 = xls[s0 * 64 + 32 + lane];
        float b1 = xls[s1 * 64 + lane],      c1 = xls[s1 * 64 + 32 + lane];
        float b2 = xls[s2 * 64 + lane],      c2 = xls[s2 * 64 + 32 + lane];
        float b3 = xls[s3 * 64 + lane],      c3 = xls[s3 * 64 + 32 + lane];
        a0 += (d0 * b0 + d1 * b1) + (d2 * b2 + d3 * b3);
        a1 += (d0 * c0 + d1 * c1) + (d2 * c2 + d3 * c3);
    }
    for (; t < end; t++) {
        int s = __ldg(&csr[t]);
        float d = __ldg(&dis[s]);
        a0 += d * xls[s * 64 + lane];
        a1 += d * xls[s * 64 + 32 + lane];
    }
    float dd = dis[w];
    P[(size_t)w * 64 + lane]      += dd * (a0 + dd * xls[w * 64 + lane]);
    P[(size_t)w * 64 + 32 + lane] += dd * (a1 + dd * xls[w * 64 + 32 + lane]);
}

__global__ void k_sage_gather(const int* __restrict__ off, const int* __restrict__ csr,
                              const float* __restrict__ xa, float* __restrict__ SA,
                              int n, int E) {
    int w = (blockIdx.x * blockDim.x + threadIdx.x) >> 5;
    int lane = threadIdx.x & 31;
    if (w >= n) return;
    int beg = off[w], end = (w == n - 1) ? E : off[w + 1];
    float a0 = 0.f, a1 = 0.f;
    int t = beg;
    for (; t + 4 <= end; t += 4) {
        int s0 = __ldg(&csr[t]),     s1 = __ldg(&csr[t + 1]);
        int s2 = __ldg(&csr[t + 2]), s3 = __ldg(&csr[t + 3]);
        float b0 = xa[s0 * 64 + lane],      c0 = xa[s0 * 64 + 32 + lane];
        float b1 = xa[s1 * 64 + lane],      c1 = xa[s1 * 64 + 32 + lane];
        float b2 = xa[s2 * 64 + lane],      c2 = xa[s2 * 64 + 32 + lane];
        float b3 = xa[s3 * 64 + lane],      c3 = xa[s3 * 64 + 32 + lane];
        a0 += (b0 + b1) + (b2 + b3);
        a1 += (c0 + c1) + (c2 + c3);
    }
    for (; t < end; t++) {
        int s = __ldg(&csr[t]);
        a0 += xa[s * 64 + lane];
        a1 += xa[s * 64 + 32 + lane];
    }
    float r = 1.0f / fmaxf((float)(end - beg), 1.0f);
    SA[(size_t)w * 64 + lane]      = a0 * r;
    SA[(size_t)w * 64 + 32 + lane] = a1 * r;
}

__global__ void k_gat_gather(const int* __restrict__ off, const int* __restrict__ csr,
                             const float* __restrict__ asrc, const float* __restrict__ adst,
                             const float* __restrict__ XS, const float* __restrict__ bias,
                             float* __restrict__ out, int n, int E) {
    int w = (blockIdx.x * blockDim.x + threadIdx.x) >> 5;
    int lane = threadIdx.x & 31;
    if (w >= n) return;
    int beg = off[w], end = (w == n - 1) ? E : off[w + 1];
    float ad = adst[w];
    float den = 0.f, a0 = 0.f, a1 = 0.f;
    int t = beg;
    for (; t + 4 <= end; t += 4) {
        int p0 = __ldg(&csr[t]),     p1 = __ldg(&csr[t + 1]);
        int p2 = __ldg(&csr[t + 2]), p3 = __ldg(&csr[t + 3]);
        float e0 = asrc[p0] + ad; e0 = (e0 > 0.f) ? e0 : 0.2f * e0;
        float e1 = asrc[p1] + ad; e1 = (e1 > 0.f) ? e1 : 0.2f * e1;
        float e2 = asrc[p2] + ad; e2 = (e2 > 0.f) ? e2 : 0.2f * e2;
        float e3 = asrc[p3] + ad; e3 = (e3 > 0.f) ? e3 : 0.2f * e3;
        float x0 = __expf(e0), x1 = __expf(e1), x2 = __expf(e2), x3 = __expf(e3);
        float b0 = XS[p0 * 64 + lane],      c0 = XS[p0 * 64 + 32 + lane];
        float b1 = XS[p1 * 64 + lane],      c1 = XS[p1 * 64 + 32 + lane];
        float b2 = XS[p2 * 64 + lane],      c2 = XS[p2 * 64 + 32 + lane];
        float b3 = XS[p3 * 64 + lane],      c3 = XS[p3 * 64 + 32 + lane];
        den += (x0 + x1) + (x2 + x3);
        a0 += (x0 * b0 + x1 * b1) + (x2 * b2 + x3 * b3);
        a1 += (x0 * c0 + x1 * c1) + (x2 * c2 + x3 * c3);
    }
    for (; t < end; t++) {
        int p = __ldg(&csr[t]);
        float e = asrc[p] + ad; e = (e > 0.f) ? e : 0.2f * e;
        float x = __expf(e);
        den += x;
        a0 += x * XS[p * 64 + lane];
        a1 += x * XS[p * 64 + 32 + lane];
    }
    float r = (den > 0.f) ? (1.0f / den) : 0.f;
    float o0 = a0 * r + bias[lane];
    float o1 = a1 * r + bias[lane + 32];
    out[(size_t)w * 64 + lane]      = fmaxf(o0, 0.f);
    out[(size_t)w * 64 + 32 + lane] = fmaxf(o1, 0.f);
}

// ---------------- cp.async double-buffered f32x2 GEMM (proven R10) ----------------
#define M_PLAIN 0
#define M_DOT   3
#define M_BIAS  4
#define XSTR 36
#define XSZ  (128 * XSTR)

template <int K, int N>
constexpr int gemm_smem_bytes() { return (2 * XSZ + 2 * 32 * N) * 4; }

template <int K, int N, int MODE>
__global__ void __launch_bounds__(256, 3) k_gemm2(
        const float* __restrict__ X, const float* __restrict__ W,
        const float* __restrict__ b0,
        const float* __restrict__ av, float* __restrict__ dotout,
        float* __restrict__ Y, int M) {
    constexpr int CPT = N / 8;
    constexpr int QP  = CPT / 2;
    constexpr int NCH = K / 32;
    extern __shared__ __align__(16) float smemf[];
    float* Xsb[2] = { smemf, smemf + XSZ };
    float* Wsb[2] = { smemf + 2 * XSZ, smemf + 2 * XSZ + 32 * N };
    unsigned xs_u32[2], ws_u32[2];
    xs_u32[0] = (unsigned)__cvta_generic_to_shared(Xsb[0]);
    xs_u32[1] = (unsigned)__cvta_generic_to_shared(Xsb[1]);
    ws_u32[0] = (unsigned)__cvta_generic_to_shared(Wsb[0]);
    ws_u32[1] = (unsigned)__cvta_generic_to_shared(Wsb[1]);

    int tid = threadIdx.x;
    int tx = tid & 7, ty = tid >> 3;
    int base = blockIdx.x * 128;

    auto stage = [&](int c, int b) {
        int kc = c * 32;
        #pragma unroll
        for (int j = 0; j < 4; j++) {
            int v = tid + j * 256;
            int r = v >> 3;
            int k0 = (v & 7) * 4;
            int rr = base + r;
            const float* src = X + (size_t)(rr < M ? rr : 0) * K + kc + k0;
            unsigned ssize = (rr < M) ? 16u : 0u;
            unsigned daddr = xs_u32[b] + (unsigned)(r * XSTR + k0) * 4u;
            asm volatile("cp.async.cg.shared.global [%0], [%1], 16, %2;"
                         :: "r"(daddr), "l"(src), "r"(ssize));
        }
        #pragma unroll
        for (int j = 0; j < N / 32; j++) {
            int v = tid + j * 256;
            int r = (v * 4) / N;
            int cc = (v * 4) % N;
            const float* src = W + (size_t)(kc + r) * N + cc;
            unsigned daddr = ws_u32[b] + (unsigned)(r * N + cc) * 4u;
            asm volatile("cp.async.cg.shared.global [%0], [%1], 16;"
                         :: "r"(daddr), "l"(src));
        }
    };

    unsigned long long accv[4][QP];
    #pragma unroll
    for (int i = 0; i < 4; i++)
        #pragma unroll
        for (int q = 0; q < QP; q++) accv[i][q] = 0ull;

    stage(0, 0);
    asm volatile("cp.async.commit_group;");

    for (int c = 0; c < NCH; c++) {
        int buf = c & 1;
        if (c + 1 < NCH) {
            stage(c + 1, (c + 1) & 1);
            asm volatile("cp.async.commit_group;");
            asm volatile("cp.async.wait_group 1;");
        } else {
            asm volatile("cp.async.wait_group 0;");
        }
        __syncthreads();
        const float* Xc = Xsb[buf];
        const float* Wc = Wsb[buf];
        #pragma unroll
        for (int k = 0; k < 32; k++) {
            unsigned long long a[4];
            #pragma unroll
            for (int i = 0; i < 4; i++) {
                unsigned a32 = *(const unsigned*)&Xc[(ty + 32 * i) * XSTR + k];
                asm("mov.b64 %0, {%1, %1};" : "=l"(a[i]) : "r"(a32));
            }
            #pragma unroll
            for (int h = 0; h < QP / 2; h++) {
                ulonglong2 wp = *(const ulonglong2*)&Wc[k * N + tx * CPT + h * 4];
                #pragma unroll
                for (int i = 0; i < 4; i++) {
                    asm("fma.rn.f32x2 %0, %1, %2, %0;"
                        : "+l"(accv[i][2 * h]) : "l"(a[i]), "l"(wp.x));
                    asm("fma.rn.f32x2 %0, %1, %2, %0;"
                        : "+l"(accv[i][2 * h + 1]) : "l"(a[i]), "l"(wp.y));
                }
            }
        }
        __syncthreads();
    }

    #pragma unroll
    for (int i = 0; i < 4; i++) {
        int row = base + ty + 32 * i;
        if (row >= M) continue;
        float d = 0.f;
        #pragma unroll
        for (int q = 0; q < QP; q++) {
            float2 v = *(float2*)&accv[i][q];
            int col = tx * CPT + 2 * q;
            if (MODE == M_BIAS) {
                float2 b = *(const float2*)&b0[col];
                v.x += b.x; v.y += b.y;
            }
            *(float2*)&Y[(size_t)row * N + col] = v;
            if (MODE == M_DOT) {
                float2 w2 = *(const float2*)&av[col];
                d += v.x * w2.x + v.y * w2.y;
            }
        }
        if (MODE == M_DOT) {
            #pragma unroll
            for (int o = 1; o < 8; o <<= 1) d += __shfl_xor_sync(0xFFFFFFFFu, d, o);
            if (tx == 0) dotout[row] = d;
        }
    }
}

// ---------------- fused layer-0 paper GEMM: K=128, N=192, 3 outputs ----------------
#define FK 128
#define FN 192
#define FXSZ (64 * XSTR)
#define FWSZ (32 * FN)
constexpr int gemmF_smem_bytes() { return (2 * FXSZ + 2 * FWSZ) * 4; }

__global__ void __launch_bounds__(256, 2) k_gemmF(
        const float* __restrict__ X, const float* __restrict__ W,
        const float* __restrict__ av, float* __restrict__ dotout,
        float* __restrict__ Y0, float* __restrict__ Y1, float* __restrict__ Y2,
        int M) {
    extern __shared__ __align__(16) float smemf[];
    float* Xsb[2] = { smemf, smemf + FXSZ };
    float* Wsb[2] = { smemf + 2 * FXSZ, smemf + 2 * FXSZ + FWSZ };
    unsigned xs_u32[2], ws_u32[2];
    xs_u32[0] = (unsigned)__cvta_generic_to_shared(Xsb[0]);
    xs_u32[1] = (unsigned)__cvta_generic_to_shared(Xsb[1]);
    ws_u32[0] = (unsigned)__cvta_generic_to_shared(Wsb[0]);
    ws_u32[1] = (unsigned)__cvta_generic_to_shared(Wsb[1]);

    int tid = threadIdx.x;
    int tx = tid & 15, ty = tid >> 4;
    int base = blockIdx.x * 64;

    auto stage = [&](int c, int b) {
        int kc = c * 32;
        #pragma unroll
        for (int j = 0; j < 2; j++) {
            int v = tid + j * 256;
            int r = v >> 3;
            int k0 = (v & 7) * 4;
            int rr = base + r;
            const float* src = X + (size_t)(rr < M ? rr : 0) * FK + kc + k0;
            unsigned ssize = (rr < M) ? 16u : 0u;
            unsigned daddr = xs_u32[b] + (unsigned)(r * XSTR + k0) * 4u;
            asm volatile("cp.async.cg.shared.global [%0], [%1], 16, %2;"
                         :: "r"(daddr), "l"(src), "r"(ssize));
        }
        #pragma unroll
        for (int j = 0; j < 6; j++) {
            int v = tid + j * 256;
            int r = v / 48;
            int cc = (v % 48) * 4;
            const float* src = W + (size_t)(kc + r) * FN + cc;
            unsigned daddr = ws_u32[b] + (unsigned)(r * FN + cc) * 4u;
            asm volatile("cp.async.cg.shared.global [%0], [%1], 16;"
                         :: "r"(daddr), "l"(src));
        }
    };

    unsigned long long accv[4][6];
    #pragma unroll
    for (int i = 0; i < 4; i++)
        #pragma unroll
        for (int q = 0; q < 6; q++) accv[i][q] = 0ull;

    stage(0, 0);
    asm volatile("cp.async.commit_group;");

    for (int c = 0; c < FK / 32; c++) {
        int buf = c & 1;
        if (c + 1 < FK / 32) {
            stage(c + 1, (c + 1) & 1);
            asm volatile("cp.async.commit_group;");
            asm volatile("cp.async.wait_group 1;");
        } else {
            asm volatile("cp.async.wait_group 0;");
        }
        __syncthreads();
        const float* Xc = Xsb[buf];
        const float* Wc = Wsb[buf];
        #pragma unroll
        for (int kk = 0; kk < 16; kk++) {
            int k = kk * 2;
            float2 ap[4];
            #pragma unroll
            for (int i = 0; i < 4; i++)
                ap[i] = *(const float2*)&Xc[(ty + 16 * i) * XSTR + k];
            #pragma unroll
            for (int s = 0; s < 2; s++) {
                unsigned long long a[4];
                #pragma unroll
                for (int i = 0; i < 4; i++) {
                    unsigned a32 = __float_as_uint(s ? ap[i].y : ap[i].x);
                    asm("mov.b64 %0, {%1, %1};" : "=l"(a[i]) : "r"(a32));
                }
                const float* wrow = &Wc[(k + s) * FN + tx * 12];
                ulonglong2 p0 = *(const ulonglong2*)(wrow);
                ulonglong2 p1 = *(const ulonglong2*)(wrow + 4);
                ulonglong2 p2 = *(const ulonglong2*)(wrow + 8);
                #pragma unroll
                for (int i = 0; i < 4; i++) {
                    asm("fma.rn.f32x2 %0, %1, %2, %0;" : "+l"(accv[i][0]) : "l"(a[i]), "l"(p0.x));
                    asm("fma.rn.f32x2 %0, %1, %2, %0;" : "+l"(accv[i][1]) : "l"(a[i]), "l"(p0.y));
                    asm("fma.rn.f32x2 %0, %1, %2, %0;" : "+l"(accv[i][2]) : "l"(a[i]), "l"(p1.x));
                    asm("fma.rn.f32x2 %0, %1, %2, %0;" : "+l"(accv[i][3]) : "l"(a[i]), "l"(p1.y));
                    asm("fma.rn.f32x2 %0, %1, %2, %0;" : "+l"(accv[i][4]) : "l"(a[i]), "l"(p2.x));
                    asm("fma.rn.f32x2 %0, %1, %2, %0;" : "+l"(accv[i][5]) : "l"(a[i]), "l"(p2.y));
                }
            }
        }
        __syncthreads();
    }

    #pragma unroll
    for (int i = 0; i < 4; i++) {
        int row = base + ty + 16 * i;
        bool ok = (row < M);
        float d = 0.f;
        #pragma unroll
        for (int q = 0; q < 6; q++) {
            float2 v = *(float2*)&accv[i][q];
            int col = tx * 12 + 2 * q;
            int sec = col >> 6;
            int within = col & 63;
            if (ok) {
                float* dst = (sec == 0) ? Y0 : ((sec == 1) ? Y1 : Y2);
                *(float2*)&dst[(size_t)row * 64 + within] = v;
                if (sec == 2) {
                    float2 w2 = *(const float2*)&av[within];
                    d += v.x * w2.x + v.y * w2.y;
                }
            }
        }
        #pragma unroll
        for (int o = 1; o < 16; o <<= 1) d += __shfl_xor_sync(0xFFFFFFFFu, d, o);
        if (tx == 0 && ok) dotout[row] = d;
    }
}

// ---------------- fused comb+XS1: xp1 = relu(SA@Wl + P + b0 + b1) kept in smem;
// XS1 = xp1 @ Ws1 ; asrc1 = XS1 . av.  xp1 never touches gmem. ----------------
#define TSTR 66
constexpr int gemmC_smem_bytes() { return gemm_smem_bytes<64, 64>(); }  // 53248 >= (128*66+4096)*4

__global__ void __launch_bounds__(256, 2) k_gemmC(
        const float* __restrict__ SA, const float* __restrict__ Wl,
        const float* __restrict__ b0, const float* __restrict__ b1,
        const float* __restrict__ P, const float* __restrict__ Ws1,
        const float* __restrict__ av, float* __restrict__ dotout,
        float* __restrict__ XS1, int M) {
    constexpr int K = 64, N = 64;
    extern __shared__ __align__(16) float smemf[];
    float* Xsb[2] = { smemf, smemf + XSZ };
    float* Wsb[2] = { smemf + 2 * XSZ, smemf + 2 * XSZ + 32 * N };
    float* tile = smemf;                       // reused after mainloop: 128*66
    float* W2   = smemf + 128 * TSTR;          // 64*64
    unsigned xs_u32[2], ws_u32[2];
    xs_u32[0] = (unsigned)__cvta_generic_to_shared(Xsb[0]);
    xs_u32[1] = (unsigned)__cvta_generic_to_shared(Xsb[1]);
    ws_u32[0] = (unsigned)__cvta_generic_to_shared(Wsb[0]);
    ws_u32[1] = (unsigned)__cvta_generic_to_shared(Wsb[1]);

    int tid = threadIdx.x;
    int tx = tid & 7, ty = tid >> 3;
    int base = blockIdx.x * 128;

    auto stage = [&](int c, int b) {
        int kc = c * 32;
        #pragma unroll
        for (int j = 0; j < 4; j++) {
            int v = tid + j * 256;
            int r = v >> 3;
            int k0 = (v & 7) * 4;
            int rr = base + r;
            const float* src = SA + (size_t)(rr < M ? rr : 0) * K + kc + k0;
            unsigned ssize = (rr < M) ? 16u : 0u;
            unsigned daddr = xs_u32[b] + (unsigned)(r * XSTR + k0) * 4u;
            asm volatile("cp.async.cg.shared.global [%0], [%1], 16, %2;"
                         :: "r"(daddr), "l"(src), "r"(ssize));
        }
        #pragma unroll
        for (int j = 0; j < 2; j++) {
            int v = tid + j * 256;
            int r = (v * 4) / N;
            int cc = (v * 4) % N;
            const float* src = Wl + (size_t)(kc + r) * N + cc;
            unsigned daddr = ws_u32[b] + (unsigned)(r * N + cc) * 4u;
            asm volatile("cp.async.cg.shared.global [%0], [%1], 16;"
                         :: "r"(daddr), "l"(src));
        }
    };

    unsigned long long accv[4][4];
    #pragma unroll
    for (int i = 0; i < 4; i++)
        #pragma unroll
        for (int q = 0; q < 4; q++) accv[i][q] = 0ull;

    stage(0, 0);
    asm volatile("cp.async.commit_group;");
    for (int c = 0; c < 2; c++) {
        int buf = c & 1;
        if (c + 1 < 2) {
            stage(1, 1);
            asm volatile("cp.async.commit_group;");
            asm volatile("cp.async.wait_group 1;");
        } else {
            asm volatile("cp.async.wait_group 0;");
        }
        __syncthreads();
        const float* Xc = Xsb[buf];
        const float* Wc = Wsb[buf];
        #pragma unroll
        for (int k = 0; k < 32; k++) {
            unsigned long long a[4];
            #pragma unroll
            for (int i = 0; i < 4; i++) {
                unsigned a32 = *(const unsigned*)&Xc[(ty + 32 * i) * XSTR + k];
                asm("mov.b64 %0, {%1, %1};" : "=l"(a[i]) : "r"(a32));
            }
            #pragma unroll
            for (int h = 0; h < 2; h++) {
                ulonglong2 wp = *(const ulonglong2*)&Wc[k * N + tx * 8 + h * 4];
                #pragma unroll
                for (int i = 0; i < 4; i++) {
                    asm("fma.rn.f32x2 %0, %1, %2, %0;"
                        : "+l"(accv[i][2 * h]) : "l"(a[i]), "l"(wp.x));
                    asm("fma.rn.f32x2 %0, %1, %2, %0;"
                        : "+l"(accv[i][2 * h + 1]) : "l"(a[i]), "l"(wp.y));
                }
            }
        }
        __syncthreads();
    }
    // mainloop done (last __syncthreads passed by all) -> smem reusable.

    // stage-1 epilogue: xp1 tile (relu(acc + P + b0 + b1)) -> smem tile
    #pragma unroll
    for (int i = 0; i < 4; i++) {
        int r = ty + 32 * i;
        int row = base + r;
        bool ok = (row < M);
        #pragma unroll
        for (int q = 0; q < 4; q++) {
            float2 v = *(float2*)&accv[i][q];
            int col = tx * 8 + 2 * q;
            if (ok) {
                float2 a2 = *(const float2*)&P[(size_t)row * 64 + col];
                float2 ba = *(const float2*)&b0[col];
                float2 bb = *(const float2*)&b1[col];
                v.x = fmaxf(v.x + a2.x + ba.x + bb.x, 0.f);
                v.y = fmaxf(v.y + a2.y + ba.y + bb.y, 0.f);
            } else {
                v.x = 0.f; v.y = 0.f;
            }
            *(float2*)&tile[r * TSTR + col] = v;
        }
    }
    // load Ws1 into W2 (64x64)
    #pragma unroll
    for (int j = 0; j < 4; j++) {
        int v = tid + j * 256;
        ((float4*)W2)[v] = ((const float4*)Ws1)[v];
    }
    __syncthreads();

    // stage 2: XS1 = tile @ Ws1, fused dot
    unsigned long long acc2[4][4];
    #pragma unroll
    for (int i = 0; i < 4; i++)
        #pragma unroll
        for (int q = 0; q < 4; q++) acc2[i][q] = 0ull;
    #pragma unroll 4
    for (int k = 0; k < 64; k++) {
        unsigned long long a[4];
        #pragma unroll
        for (int i = 0; i < 4; i++) {
            unsigned a32 = *(const unsigned*)&tile[(ty + 32 * i) * TSTR + k];
            asm("mov.b64 %0, {%1, %1};" : "=l"(a[i]) : "r"(a32));
        }
        #pragma unroll
        for (int h = 0; h < 2; h++) {
            ulonglong2 wp = *(const ulonglong2*)&W2[k * 64 + tx * 8 + h * 4];
            #pragma unroll
            for (int i = 0; i < 4; i++) {
                asm("fma.rn.f32x2 %0, %1, %2, %0;"
                    : "+l"(acc2[i][2 * h]) : "l"(a[i]), "l"(wp.x));
                asm("fma.rn.f32x2 %0, %1, %2, %0;"
                    : "+l"(acc2[i][2 * h + 1]) : "l"(a[i]), "l"(wp.y));
            }
        }
    }
    #pragma unroll
    for (int i = 0; i < 4; i++) {
        int row = base + ty + 32 * i;
        if (row >= M) continue;
        float d = 0.f;
        #pragma unroll
        for (int q = 0; q < 4; q++) {
            float2 v = *(float2*)&acc2[i][q];
            int col = tx * 8 + 2 * q;
            *(float2*)&XS1[(size_t)row * 64 + col] = v;
            float2 w2 = *(const float2*)&av[col];
            d += v.x * w2.x + v.y * w2.y;
        }
        #pragma unroll
        for (int o = 1; o < 8; o <<= 1) d += __shfl_xor_sync(0xFFFFFFFFu, d, o);
        if (tx == 0) dotout[row] = d;
    }
}

// ---------------- host ----------------
static inline int cdiv(long long a, int b) { return (int)((a + b - 1) / b); }

extern "C" void kernel_launch(void* const* d_in, const int* in_sizes, int n_in,
                              void* d_out, int out_size) {
    const float* xp       = (const float*)d_in[0];
    const float* xa       = (const float*)d_in[1];
    const float* gcn_W0   = (const float*)d_in[2];
    const float* gcn_b0   = (const float*)d_in[3];
    const float* sage_Wl0 = (const float*)d_in[4];
    const float* sage_bl0 = (const float*)d_in[5];
    const float* sage_Wr0 = (const float*)d_in[6];
    const float* gat_Ws0  = (const float*)d_in[7];
    const float* gat_Wd0  = (const float*)d_in[8];
    const float* gat_as0  = (const float*)d_in[9];
    const float* gat_ad0  = (const float*)d_in[10];
    const float* gat_b0   = (const float*)d_in[11];
    const float* gat_Ws1  = (const float*)d_in[17];
    const float* gat_Wd1  = (const float*)d_in[18];
    const float* gat_as1  = (const float*)d_in[19];
    const float* gat_ad1  = (const float*)d_in[20];
    const float* gat_b1   = (const float*)d_in[21];
    const float* lin_W    = (const float*)d_in[22];
    const float* lin_b    = (const float*)d_in[23];
    const int* cs = (const int*)d_in[24];
    const int* cd = (const int*)d_in[25];
    const int* ws = (const int*)d_in[26];  // author idx of writes edge
    const int* wd = (const int*)d_in[27];  // paper idx of writes edge
    float* out = (float*)d_out;

    void* p;
    #define SYM(name) cudaGetSymbolAddress(&p, g_##name)
    SYM(xls);   float* xls  = (float*)p;
    SYM(P);     float* P    = (float*)p;
    SYM(SA);    float* SA   = (float*)p;
    SYM(XS);    float* XS   = (float*)p;
    SYM(XS1);   float* XS1  = (float*)p;
    SYM(XD);    float* XD   = (float*)p;
    SYM(xa1);   float* xa1  = (float*)p;
    SYM(Wcat);  float* Wcat = (float*)p;
    SYM(dis);   float* dis  = (float*)p;
    SYM(asrc);  float* asrc = (float*)p;
    SYM(adst);  float* adst = (float*)p;
    SYM(asrc1); float* asrc1 = (float*)p;
    SYM(adst1); float* adst1 = (float*)p;
    SYM(degC); int* degC = (int*)p;
    SYM(degWp); int* degWp = (int*)p;
    SYM(degWa); int* degWa = (int*)p;
    SYM(offC); int* offC = (int*)p;
    SYM(offWp); int* offWp = (int*)p;
    SYM(offWa); int* offWa = (int*)p;
    SYM(curC); int* curC = (int*)p;
    SYM(curWp); int* curWp = (int*)p;
    SYM(curWa); int* curWa = (int*)p;
    SYM(bsumA); int* bsumA = (int*)p;
    SYM(bsumB); int* bsumB = (int*)p;
    SYM(csrC); int* csrC = (int*)p;
    SYM(csrWp); int* csrWp = (int*)p;
    SYM(csrWa); int* csrWa = (int*)p;
    #undef SYM

    cudaFuncSetAttribute(k_gemmF,
        cudaFuncAttributeMaxDynamicSharedMemorySize, gemmF_smem_bytes());
    cudaFuncSetAttribute(k_gemmC,
        cudaFuncAttributeMaxDynamicSharedMemorySize, gemmC_smem_bytes());
    cudaFuncSetAttribute(k_gemm2<64, 64, M_DOT>,
        cudaFuncAttributeMaxDynamicSharedMemorySize, gemm_smem_bytes<64, 64>());
    cudaFuncSetAttribute(k_gemm2<64, 32, M_BIAS>,
        cudaFuncAttributeMaxDynamicSharedMemorySize, gemm_smem_bytes<64, 32>());

    const int T = 256;
    cudaStream_t s0 = 0, sA, sB;
    cudaStreamCreateWithFlags(&sA, cudaStreamNonBlocking);
    cudaStreamCreateWithFlags(&sB, cudaStreamNonBlocking);
    cudaEvent_t eF, eG2, eG4, eSA, eGcn, eAuth;
    cudaEventCreateWithFlags(&eF,   cudaEventDisableTiming);
    cudaEventCreateWithFlags(&eG2,  cudaEventDisableTiming);
    cudaEventCreateWithFlags(&eG4,  cudaEventDisableTiming);
    cudaEventCreateWithFlags(&eSA,  cudaEventDisableTiming);
    cudaEventCreateWithFlags(&eGcn, cudaEventDisableTiming);
    cudaEventCreateWithFlags(&eAuth, cudaEventDisableTiming);

    #define GEMM(Kk, Nn, MODE, STRM, Xs, Ws_, B0, AV, DOT, Yy, Mm) \
        k_gemm2<Kk, Nn, MODE><<<cdiv(Mm, 128), 256, (gemm_smem_bytes<Kk, Nn>()), STRM>>>( \
            Xs, Ws_, B0, AV, DOT, Yy, Mm)

    // ================= fork (R12 schedule) =================
    cudaEventRecord(eF, s0);
    cudaStreamWaitEvent(sA, eF, 0);
    cudaStreamWaitEvent(sB, eF, 0);

    // ---- s0: fused layer-0 paper GEMM (gcn|sageWr|gatWs + asrc dot), then XD0 ----
    k_wcat<<<cdiv(128 * 192, T), T, 0, s0>>>(gcn_W0, sage_Wr0, gat_Ws0, Wcat);
    k_gemmF<<<cdiv(NP, 64), 256, gemmF_smem_bytes(), s0>>>(
        xp, Wcat, gat_as0, asrc, xls, P, XS, NP);
    cudaEventRecord(eG2, s0);   // xls + P + XS + asrc ready
    GEMM(64, 64, M_DOT, s0, xa, gat_Wd0, nullptr, gat_ad0, adst, XD, NA);
    cudaEventRecord(eG4, s0);   // XS/asrc/adst ready

    // ---- sA: cites CSR build, then gcn_gather as soon as xls+P ready ----
    k_zero_i<<<cdiv(NP, T), T, 0, sA>>>(degC, NP);
    k_count<<<cdiv(EC, T), T, 0, sA>>>(cd, degC, EC);
    k_dis<<<cdiv(NP, T), T, 0, sA>>>(degC, dis, NP);
    k_scan1<<<cdiv(NP, 512), 512, 0, sA>>>(degC, offC, bsumA, NP);
    k_scan2<<<1, 512, 0, sA>>>(bsumA, cdiv(NP, 512));
    k_scan3<<<cdiv(NP, T), T, 0, sA>>>(offC, curC, bsumA, NP);
    k_fill<<<cdiv(EC, T), T, 0, sA>>>(cd, cs, curC, csrC, EC);
    cudaStreamWaitEvent(sA, eG2, 0);
    k_gcn_gather<<<cdiv((long long)NP * 32, T), T, 0, sA>>>(offC, csrC, xls, dis, P, NP, EC);
    cudaEventRecord(eGcn, sA);

    // ---- sB: writes CSRs; sage_gather; author branch ----
    k_zero_i<<<cdiv(NP, T), T, 0, sB>>>(degWp, NP);
    k_count<<<cdiv(EW, T), T, 0, sB>>>(wd, degWp, EW);
    k_scan1<<<cdiv(NP, 512), 512, 0, sB>>>(degWp, offWp, bsumB, NP);
    k_scan2<<<1, 512, 0, sB>>>(bsumB, cdiv(NP, 512));
    k_scan3<<<cdiv(NP, T), T, 0, sB>>>(offWp, curWp, bsumB, NP);
    k_fill<<<cdiv(EW, T), T, 0, sB>>>(wd, ws, curWp, csrWp, EW);
    k_sage_gather<<<cdiv((long long)NP * 32, T), T, 0, sB>>>(offWp, csrWp, xa, SA, NP, EW);
    cudaEventRecord(eSA, sB);
    k_zero_i<<<cdiv(NA, T), T, 0, sB>>>(degWa, NA);
    k_count<<<cdiv(EW, T), T, 0, sB>>>(ws, degWa, EW);
    k_scan1<<<cdiv(NA, 512), 512, 0, sB>>>(degWa, offWa, bsumB, NA);
    k_scan2<<<1, 512, 0, sB>>>(bsumB, cdiv(NA, 512));
    k_scan3<<<cdiv(NA, T), T, 0, sB>>>(offWa, curWa, bsumB, NA);
    k_fill<<<cdiv(EW, T), T, 0, sB>>>(ws, wd, curWa, csrWa, EW);
    cudaStreamWaitEvent(sB, eG4, 0);
    k_gat_gather<<<cdiv((long long)NA * 32, T), T, 0, sB>>>(offWa, csrWa, asrc, adst, XS,
                                                            gat_b0, xa1, NA, EW);
    GEMM(64, 64, M_DOT, sB, xa1, gat_Wd1, nullptr, gat_ad1, adst1, XD, NA);
    cudaEventRecord(eAuth, sB);

    // ---- s0 (paper branch): fused comb+XS1, then final GAT + head ----
    cudaStreamWaitEvent(s0, eSA, 0);
    cudaStreamWaitEvent(s0, eGcn, 0);
    k_gemmC<<<cdiv(NP, 128), 256, gemmC_smem_bytes(), s0>>>(
        SA, sage_Wl0, gcn_b0, sage_bl0, P, gat_Ws1, gat_as1, asrc1, XS1, NP);
    cudaStreamWaitEvent(s0, eAuth, 0);
    k_gat_gather<<<cdiv((long long)NA * 32, T), T, 0, s0>>>(offWa, csrWa, asrc1, adst1, XS1,
                                                            gat_b1, xa1, NA, EW);
    GEMM(64, 32, M_BIAS, s0, xa1, lin_W, lin_b, nullptr, nullptr, out, NA);
    #undef GEMM

    // destroy only outside capture
    cudaStreamCaptureStatus st = cudaStreamCaptureStatusNone;
    cudaStreamIsCapturing(sA, &st);
    if (st == cudaStreamCaptureStatusNone) {
        cudaEventDestroy(eF);  cudaEventDestroy(eG2); cudaEventDestroy(eG4);
        cudaEventDestroy(eSA); cudaEventDestroy(eGcn); cudaEventDestroy(eAuth);
        cudaStreamDestroy(sA); cudaStreamDestroy(sB);
    }
}

// round 16
// speedup vs baseline: 1.4204x; 1.0385x over previous
#include <cuda_runtime.h>
#include <cuda_fp16.h>
#include <cstdint>
#include <cstddef>

#define NP 200000
#define NA 100000
#define EC 4000000
#define EW 2000000

// ---------------- device scratch (allocation-free) ----------------
__device__ __half g_xls16[(size_t)NP * 64];  // fp16 x_paper @ gcn_W (gathered)
__device__ __half g_XS16 [(size_t)NP * 64];  // fp16 gat L0 source feats (gathered)
__device__ __half g_XS116[(size_t)NP * 64];  // fp16 gat L1 source feats (gathered)
__device__ float g_P  [(size_t)NP * 64];   // paper accumulation (fp32)
__device__ float g_SA [(size_t)NP * 64];   // sage neighbor mean
__device__ float g_XD [(size_t)NA * 64];   // gat dst feats (author)
__device__ float g_xa1[(size_t)NA * 64];   // x_author after layer 0/1
__device__ float g_Wcat[128 * 192];        // [gcn_W0 | sage_Wr0 | gat_Ws0]
__device__ float g_dis [NP];
__device__ float g_asrc[NP],  g_adst[NA];
__device__ float g_asrc1[NP], g_adst1[NA];
__device__ int g_degC[NP], g_degWp[NP], g_degWa[NA];
__device__ int g_offC[NP], g_offWp[NP], g_offWa[NA];
__device__ int g_curC[NP], g_curWp[NP], g_curWa[NA];
__device__ int g_bsumA[512], g_bsumB[512];
__device__ int g_csrC[EC], g_csrWp[EW], g_csrWa[EW];

// ---------------- utility kernels ----------------
__global__ void k_zero_i(int* p, int n) {
    int i = blockIdx.x * blockDim.x + threadIdx.x;
    if (i < n) p[i] = 0;
}
__global__ void k_count(const int* __restrict__ idx, int* cnt, int E) {
    int i = blockIdx.x * blockDim.x + threadIdx.x;
    if (i < E) atomicAdd(&cnt[idx[i]], 1);
}
__global__ void k_dis(const int* __restrict__ cnt, float* dis, int n) {
    int i = blockIdx.x * blockDim.x + threadIdx.x;
    if (i < n) dis[i] = rsqrtf((float)cnt[i] + 1.0f);
}
__global__ void k_wcat(const float* __restrict__ w0, const float* __restrict__ w1,
                       const float* __restrict__ w2, float* __restrict__ out) {
    int i = blockIdx.x * blockDim.x + threadIdx.x;
    if (i >= 128 * 192) return;
    int k = i / 192, c = i % 192;
    float v = (c < 64) ? w0[k * 64 + c]
            : (c < 128) ? w1[k * 64 + (c - 64)]
            : w2[k * 64 + (c - 128)];
    out[i] = v;
}

// ---------------- scan (3-phase, blocks of 512) ----------------
__global__ void k_scan1(const int* __restrict__ deg, int* off, int* bsum, int n) {
    __shared__ int sh[512];
    int t = threadIdx.x, i = blockIdx.x * 512 + t;
    int v = (i < n) ? deg[i] : 0;
    sh[t] = v; __syncthreads();
    #pragma unroll
    for (int o = 1; o < 512; o <<= 1) {
        int x = (t >= o) ? sh[t - o] : 0;
        __syncthreads(); sh[t] += x; __syncthreads();
    }
    if (i < n) off[i] = sh[t] - v;
    if (t == 511) bsum[blockIdx.x] = sh[511];
}
__global__ void k_scan2(int* bsum, int nb) {
    __shared__ int sh[512];
    int t = threadIdx.x;
    int v = (t < nb) ? bsum[t] : 0;
    sh[t] = v; __syncthreads();
    #pragma unroll
    for (int o = 1; o < 512; o <<= 1) {
        int x = (t >= o) ? sh[t - o] : 0;
        __syncthreads(); sh[t] += x; __syncthreads();
    }
    if (t < nb) bsum[t] = sh[t] - v;
}
__global__ void k_scan3(int* off, int* cur, const int* __restrict__ bsum, int n) {
    int i = blockIdx.x * blockDim.x + threadIdx.x;
    if (i < n) { int v = off[i] + bsum[i >> 9]; off[i] = v; cur[i] = v; }
}
__global__ void k_fill(const int* __restrict__ dst, const int* __restrict__ src,
                       int* cur, int* csr, int E) {
    int i = blockIdx.x * blockDim.x + threadIdx.x;
    if (i < E) {
        int pos = atomicAdd(&cur[dst[i]], 1);
        csr[pos] = src[i];
    }
}

// ---------------- gathers ----------------
// fp16 feature rows; lane handles cols 2*lane, 2*lane+1 (one half2 per edge per lane)
__global__ void k_gcn_gather(const int* __restrict__ off, const int* __restrict__ csr,
                             const __half2* __restrict__ x2, const float* __restrict__ dis,
                             float* __restrict__ P, int n, int E) {
    int w = (blockIdx.x * blockDim.x + threadIdx.x) >> 5;
    int lane = threadIdx.x & 31;
    if (w >= n) return;
    int beg = off[w], end = (w == n - 1) ? E : off[w + 1];
    float a0 = 0.f, a1 = 0.f;
    int t = beg;
    for (; t + 4 <= end; t += 4) {
        int s0 = __ldg(&csr[t]),     s1 = __ldg(&csr[t + 1]);
        int s2 = __ldg(&csr[t + 2]), s3 = __ldg(&csr[t + 3]);
        float d0 = __ldg(&dis[s0]), d1 = __ldg(&dis[s1]);
        float d2 = __ldg(&dis[s2]), d3 = __ldg(&dis[s3]);
        float2 f0 = __half22float2(x2[s0 * 32 + lane]);
        float2 f1 = __half22float2(x2[s1 * 32 + lane]);
        float2 f2 = __half22float2(x2[s2 * 32 + lane]);
        float2 f3 = __half22float2(x2[s3 * 32 + lane]);
        a0 += (d0 * f0.x + d1 * f1.x) + (d2 * f2.x + d3 * f3.x);
        a1 += (d0 * f0.y + d1 * f1.y) + (d2 * f2.y + d3 * f3.y);
    }
    for (; t < end; t++) {
        int s = __ldg(&csr[t]);
        float d = __ldg(&dis[s]);
        float2 f = __half22float2(x2[s * 32 + lane]);
        a0 += d * f.x;
        a1 += d * f.y;
    }
    float dd = dis[w];
    float2 fs = __half22float2(x2[w * 32 + lane]);
    float2 pv = *(float2*)&P[(size_t)w * 64 + 2 * lane];
    pv.x += dd * (a0 + dd * fs.x);
    pv.y += dd * (a1 + dd * fs.y);
    *(float2*)&P[(size_t)w * 64 + 2 * lane] = pv;
}

__global__ void k_sage_gather(const int* __restrict__ off, const int* __restrict__ csr,
                              const float* __restrict__ xa, float* __restrict__ SA,
                              int n, int E) {
    int w = (blockIdx.x * blockDim.x + threadIdx.x) >> 5;
    int lane = threadIdx.x & 31;
    if (w >= n) return;
    int beg = off[w], end = (w == n - 1) ? E : off[w + 1];
    float a0 = 0.f, a1 = 0.f;
    int t = beg;
    for (; t + 4 <= end; t += 4) {
        int s0 = __ldg(&csr[t]),     s1 = __ldg(&csr[t + 1]);
        int s2 = __ldg(&csr[t + 2]), s3 = __ldg(&csr[t + 3]);
        float b0 = xa[s0 * 64 + lane],      c0 = xa[s0 * 64 + 32 + lane];
        float b1 = xa[s1 * 64 + lane],      c1 = xa[s1 * 64 + 32 + lane];
        float b2 = xa[s2 * 64 + lane],      c2 = xa[s2 * 64 + 32 + lane];
        float b3 = xa[s3 * 64 + lane],      c3 = xa[s3 * 64 + 32 + lane];
        a0 += (b0 + b1) + (b2 + b3);
        a1 += (c0 + c1) + (c2 + c3);
    }
    for (; t < end; t++) {
        int s = __ldg(&csr[t]);
        a0 += xa[s * 64 + lane];
        a1 += xa[s * 64 + 32 + lane];
    }
    float r = 1.0f / fmaxf((float)(end - beg), 1.0f);
    SA[(size_t)w * 64 + lane]      = a0 * r;
    SA[(size_t)w * 64 + 32 + lane] = a1 * r;
}

// fused GAT: fp16 XS rows, lane handles cols 2*lane, 2*lane+1
__global__ void k_gat_gather(const int* __restrict__ off, const int* __restrict__ csr,
                             const float* __restrict__ asrc, const float* __restrict__ adst,
                             const __half2* __restrict__ X2, const float* __restrict__ bias,
                             float* __restrict__ out, int n, int E) {
    int w = (blockIdx.x * blockDim.x + threadIdx.x) >> 5;
    int lane = threadIdx.x & 31;
    if (w >= n) return;
    int beg = off[w], end = (w == n - 1) ? E : off[w + 1];
    float ad = adst[w];
    float den = 0.f, a0 = 0.f, a1 = 0.f;
    int t = beg;
    for (; t + 4 <= end; t += 4) {
        int p0 = __ldg(&csr[t]),     p1 = __ldg(&csr[t + 1]);
        int p2 = __ldg(&csr[t + 2]), p3 = __ldg(&csr[t + 3]);
        float e0 = asrc[p0] + ad; e0 = (e0 > 0.f) ? e0 : 0.2f * e0;
        float e1 = asrc[p1] + ad; e1 = (e1 > 0.f) ? e1 : 0.2f * e1;
        float e2 = asrc[p2] + ad; e2 = (e2 > 0.f) ? e2 : 0.2f * e2;
        float e3 = asrc[p3] + ad; e3 = (e3 > 0.f) ? e3 : 0.2f * e3;
        float x0 = __expf(e0), x1 = __expf(e1), x2 = __expf(e2), x3 = __expf(e3);
        float2 f0 = __half22float2(X2[p0 * 32 + lane]);
        float2 f1 = __half22float2(X2[p1 * 32 + lane]);
        float2 f2 = __half22float2(X2[p2 * 32 + lane]);
        float2 f3 = __half22float2(X2[p3 * 32 + lane]);
        den += (x0 + x1) + (x2 + x3);
        a0 += (x0 * f0.x + x1 * f1.x) + (x2 * f2.x + x3 * f3.x);
        a1 += (x0 * f0.y + x1 * f1.y) + (x2 * f2.y + x3 * f3.y);
    }
    for (; t < end; t++) {
        int p = __ldg(&csr[t]);
        float e = asrc[p] + ad; e = (e > 0.f) ? e : 0.2f * e;
        float x = __expf(e);
        float2 f = __half22float2(X2[p * 32 + lane]);
        den += x;
        a0 += x * f.x;
        a1 += x * f.y;
    }
    float r = (den > 0.f) ? (1.0f / den) : 0.f;
    float2 b = *(const float2*)&bias[2 * lane];
    float2 o;
    o.x = fmaxf(a0 * r + b.x, 0.f);
    o.y = fmaxf(a1 * r + b.y, 0.f);
    *(float2*)&out[(size_t)w * 64 + 2 * lane] = o;
}

// ---------------- cp.async double-buffered f32x2 GEMM (proven R10) ----------------
#define M_PLAIN 0
#define M_DOT   3
#define M_BIAS  4
#define XSTR 36
#define XSZ  (128 * XSTR)

template <int K, int N>
constexpr int gemm_smem_bytes() { return (2 * XSZ + 2 * 32 * N) * 4; }

template <int K, int N, int MODE>
__global__ void __launch_bounds__(256, 3) k_gemm2(
        const float* __restrict__ X, const float* __restrict__ W,
        const float* __restrict__ b0,
        const float* __restrict__ av, float* __restrict__ dotout,
        float* __restrict__ Y, int M) {
    constexpr int CPT = N / 8;
    constexpr int QP  = CPT / 2;
    constexpr int NCH = K / 32;
    extern __shared__ __align__(16) float smemf[];
    float* Xsb[2] = { smemf, smemf + XSZ };
    float* Wsb[2] = { smemf + 2 * XSZ, smemf + 2 * XSZ + 32 * N };
    unsigned xs_u32[2], ws_u32[2];
    xs_u32[0] = (unsigned)__cvta_generic_to_shared(Xsb[0]);
    xs_u32[1] = (unsigned)__cvta_generic_to_shared(Xsb[1]);
    ws_u32[0] = (unsigned)__cvta_generic_to_shared(Wsb[0]);
    ws_u32[1] = (unsigned)__cvta_generic_to_shared(Wsb[1]);

    int tid = threadIdx.x;
    int tx = tid & 7, ty = tid >> 3;
    int base = blockIdx.x * 128;

    auto stage = [&](int c, int b) {
        int kc = c * 32;
        #pragma unroll
        for (int j = 0; j < 4; j++) {
            int v = tid + j * 256;
            int r = v >> 3;
            int k0 = (v & 7) * 4;
            int rr = base + r;
            const float* src = X + (size_t)(rr < M ? rr : 0) * K + kc + k0;
            unsigned ssize = (rr < M) ? 16u : 0u;
            unsigned daddr = xs_u32[b] + (unsigned)(r * XSTR + k0) * 4u;
            asm volatile("cp.async.cg.shared.global [%0], [%1], 16, %2;"
                         :: "r"(daddr), "l"(src), "r"(ssize));
        }
        #pragma unroll
        for (int j = 0; j < N / 32; j++) {
            int v = tid + j * 256;
            int r = (v * 4) / N;
            int cc = (v * 4) % N;
            const float* src = W + (size_t)(kc + r) * N + cc;
            unsigned daddr = ws_u32[b] + (unsigned)(r * N + cc) * 4u;
            asm volatile("cp.async.cg.shared.global [%0], [%1], 16;"
                         :: "r"(daddr), "l"(src));
        }
    };

    unsigned long long accv[4][QP];
    #pragma unroll
    for (int i = 0; i < 4; i++)
        #pragma unroll
        for (int q = 0; q < QP; q++) accv[i][q] = 0ull;

    stage(0, 0);
    asm volatile("cp.async.commit_group;");

    for (int c = 0; c < NCH; c++) {
        int buf = c & 1;
        if (c + 1 < NCH) {
            stage(c + 1, (c + 1) & 1);
            asm volatile("cp.async.commit_group;");
            asm volatile("cp.async.wait_group 1;");
        } else {
            asm volatile("cp.async.wait_group 0;");
        }
        __syncthreads();
        const float* Xc = Xsb[buf];
        const float* Wc = Wsb[buf];
        #pragma unroll
        for (int k = 0; k < 32; k++) {
            unsigned long long a[4];
            #pragma unroll
            for (int i = 0; i < 4; i++) {
                unsigned a32 = *(const unsigned*)&Xc[(ty + 32 * i) * XSTR + k];
                asm("mov.b64 %0, {%1, %1};" : "=l"(a[i]) : "r"(a32));
            }
            #pragma unroll
            for (int h = 0; h < QP / 2; h++) {
                ulonglong2 wp = *(const ulonglong2*)&Wc[k * N + tx * CPT + h * 4];
                #pragma unroll
                for (int i = 0; i < 4; i++) {
                    asm("fma.rn.f32x2 %0, %1, %2, %0;"
                        : "+l"(accv[i][2 * h]) : "l"(a[i]), "l"(wp.x));
                    asm("fma.rn.f32x2 %0, %1, %2, %0;"
                        : "+l"(accv[i][2 * h + 1]) : "l"(a[i]), "l"(wp.y));
                }
            }
        }
        __syncthreads();
    }

    #pragma unroll
    for (int i = 0; i < 4; i++) {
        int row = base + ty + 32 * i;
        if (row >= M) continue;
        float d = 0.f;
        #pragma unroll
        for (int q = 0; q < QP; q++) {
            float2 v = *(float2*)&accv[i][q];
            int col = tx * CPT + 2 * q;
            if (MODE == M_BIAS) {
                float2 b = *(const float2*)&b0[col];
                v.x += b.x; v.y += b.y;
            }
            *(float2*)&Y[(size_t)row * N + col] = v;
            if (MODE == M_DOT) {
                float2 w2 = *(const float2*)&av[col];
                d += v.x * w2.x + v.y * w2.y;
            }
        }
        if (MODE == M_DOT) {
            #pragma unroll
            for (int o = 1; o < 8; o <<= 1) d += __shfl_xor_sync(0xFFFFFFFFu, d, o);
            if (tx == 0) dotout[row] = d;
        }
    }
}

// ---------------- fused layer-0 paper GEMM: K=128, N=192, 3 outputs ----------------
// cols 0-63 -> xls16 (fp16), 64-127 -> P (fp32), 128-191 -> XS16 (fp16) + asrc dot
#define FK 128
#define FN 192
#define FXSZ (64 * XSTR)
#define FWSZ (32 * FN)
constexpr int gemmF_smem_bytes() { return (2 * FXSZ + 2 * FWSZ) * 4; }

__global__ void __launch_bounds__(256, 2) k_gemmF(
        const float* __restrict__ X, const float* __restrict__ W,
        const float* __restrict__ av, float* __restrict__ dotout,
        __half* __restrict__ Y0, float* __restrict__ Y1, __half* __restrict__ Y2,
        int M) {
    extern __shared__ __align__(16) float smemf[];
    float* Xsb[2] = { smemf, smemf + FXSZ };
    float* Wsb[2] = { smemf + 2 * FXSZ, smemf + 2 * FXSZ + FWSZ };
    unsigned xs_u32[2], ws_u32[2];
    xs_u32[0] = (unsigned)__cvta_generic_to_shared(Xsb[0]);
    xs_u32[1] = (unsigned)__cvta_generic_to_shared(Xsb[1]);
    ws_u32[0] = (unsigned)__cvta_generic_to_shared(Wsb[0]);
    ws_u32[1] = (unsigned)__cvta_generic_to_shared(Wsb[1]);

    int tid = threadIdx.x;
    int tx = tid & 15, ty = tid >> 4;
    int base = blockIdx.x * 64;

    auto stage = [&](int c, int b) {
        int kc = c * 32;
        #pragma unroll
        for (int j = 0; j < 2; j++) {
            int v = tid + j * 256;
            int r = v >> 3;
            int k0 = (v & 7) * 4;
            int rr = base + r;
            const float* src = X + (size_t)(rr < M ? rr : 0) * FK + kc + k0;
            unsigned ssize = (rr < M) ? 16u : 0u;
            unsigned daddr = xs_u32[b] + (unsigned)(r * XSTR + k0) * 4u;
            asm volatile("cp.async.cg.shared.global [%0], [%1], 16, %2;"
                         :: "r"(daddr), "l"(src), "r"(ssize));
        }
        #pragma unroll
        for (int j = 0; j < 6; j++) {
            int v = tid + j * 256;
            int r = v / 48;
            int cc = (v % 48) * 4;
            const float* src = W + (size_t)(kc + r) * FN + cc;
            unsigned daddr = ws_u32[b] + (unsigned)(r * FN + cc) * 4u;
            asm volatile("cp.async.cg.shared.global [%0], [%1], 16;"
                         :: "r"(daddr), "l"(src));
        }
    };

    unsigned long long accv[4][6];
    #pragma unroll
    for (int i = 0; i < 4; i++)
        #pragma unroll
        for (int q = 0; q < 6; q++) accv[i][q] = 0ull;

    stage(0, 0);
    asm volatile("cp.async.commit_group;");

    for (int c = 0; c < FK / 32; c++) {
        int buf = c & 1;
        if (c + 1 < FK / 32) {
            stage(c + 1, (c + 1) & 1);
            asm volatile("cp.async.commit_group;");
            asm volatile("cp.async.wait_group 1;");
        } else {
            asm volatile("cp.async.wait_group 0;");
        }
        __syncthreads();
        const float* Xc = Xsb[buf];
        const float* Wc = Wsb[buf];
        #pragma unroll
        for (int kk = 0; kk < 16; kk++) {
            int k = kk * 2;
            float2 ap[4];
            #pragma unroll
            for (int i = 0; i < 4; i++)
                ap[i] = *(const float2*)&Xc[(ty + 16 * i) * XSTR + k];
            #pragma unroll
            for (int s = 0; s < 2; s++) {
                unsigned long long a[4];
                #pragma unroll
                for (int i = 0; i < 4; i++) {
                    unsigned a32 = __float_as_uint(s ? ap[i].y : ap[i].x);
                    asm("mov.b64 %0, {%1, %1};" : "=l"(a[i]) : "r"(a32));
                }
                const float* wrow = &Wc[(k + s) * FN + tx * 12];
                ulonglong2 p0 = *(const ulonglong2*)(wrow);
                ulonglong2 p1 = *(const ulonglong2*)(wrow + 4);
                ulonglong2 p2 = *(const ulonglong2*)(wrow + 8);
                #pragma unroll
                for (int i = 0; i < 4; i++) {
                    asm("fma.rn.f32x2 %0, %1, %2, %0;" : "+l"(accv[i][0]) : "l"(a[i]), "l"(p0.x));
                    asm("fma.rn.f32x2 %0, %1, %2, %0;" : "+l"(accv[i][1]) : "l"(a[i]), "l"(p0.y));
                    asm("fma.rn.f32x2 %0, %1, %2, %0;" : "+l"(accv[i][2]) : "l"(a[i]), "l"(p1.x));
                    asm("fma.rn.f32x2 %0, %1, %2, %0;" : "+l"(accv[i][3]) : "l"(a[i]), "l"(p1.y));
                    asm("fma.rn.f32x2 %0, %1, %2, %0;" : "+l"(accv[i][4]) : "l"(a[i]), "l"(p2.x));
                    asm("fma.rn.f32x2 %0, %1, %2, %0;" : "+l"(accv[i][5]) : "l"(a[i]), "l"(p2.y));
                }
            }
        }
        __syncthreads();
    }

    #pragma unroll
    for (int i = 0; i < 4; i++) {
        int row = base + ty + 16 * i;
        bool ok = (row < M);
        float d = 0.f;
        #pragma unroll
        for (int q = 0; q < 6; q++) {
            float2 v = *(float2*)&accv[i][q];
            int col = tx * 12 + 2 * q;
            int sec = col >> 6;
            int within = col & 63;
            if (ok) {
                if (sec == 0) {
                    *(__half2*)&Y0[(size_t)row * 64 + within] = __floats2half2_rn(v.x, v.y);
                } else if (sec == 1) {
                    *(float2*)&Y1[(size_t)row * 64 + within] = v;
                } else {
                    *(__half2*)&Y2[(size_t)row * 64 + within] = __floats2half2_rn(v.x, v.y);
                    float2 w2 = *(const float2*)&av[within];
                    d += v.x * w2.x + v.y * w2.y;
                }
            }
        }
        #pragma unroll
        for (int o = 1; o < 16; o <<= 1) d += __shfl_xor_sync(0xFFFFFFFFu, d, o);
        if (tx == 0 && ok) dotout[row] = d;
    }
}

// ---------------- fused comb+XS1: xp1 = relu(SA@Wl + P + b0 + b1) in smem;
// XS1 (fp16) = xp1 @ Ws1 ; asrc1 = XS1 . av. ----------------
#define TSTR 66
constexpr int gemmC_smem_bytes() { return gemm_smem_bytes<64, 64>(); }

__global__ void __launch_bounds__(256, 2) k_gemmC(
        const float* __restrict__ SA, const float* __restrict__ Wl,
        const float* __restrict__ b0, const float* __restrict__ b1,
        const float* __restrict__ P, const float* __restrict__ Ws1,
        const float* __restrict__ av, float* __restrict__ dotout,
        __half* __restrict__ XS1, int M) {
    constexpr int K = 64, N = 64;
    extern __shared__ __align__(16) float smemf[];
    float* Xsb[2] = { smemf, smemf + XSZ };
    float* Wsb[2] = { smemf + 2 * XSZ, smemf + 2 * XSZ + 32 * N };
    float* tile = smemf;
    float* W2   = smemf + 128 * TSTR;
    unsigned xs_u32[2], ws_u32[2];
    xs_u32[0] = (unsigned)__cvta_generic_to_shared(Xsb[0]);
    xs_u32[1] = (unsigned)__cvta_generic_to_shared(Xsb[1]);
    ws_u32[0] = (unsigned)__cvta_generic_to_shared(Wsb[0]);
    ws_u32[1] = (unsigned)__cvta_generic_to_shared(Wsb[1]);

    int tid = threadIdx.x;
    int tx = tid & 7, ty = tid >> 3;
    int base = blockIdx.x * 128;

    auto stage = [&](int c, int b) {
        int kc = c * 32;
        #pragma unroll
        for (int j = 0; j < 4; j++) {
            int v = tid + j * 256;
            int r = v >> 3;
            int k0 = (v & 7) * 4;
            int rr = base + r;
            const float* src = SA + (size_t)(rr < M ? rr : 0) * K + kc + k0;
            unsigned ssize = (rr < M) ? 16u : 0u;
            unsigned daddr = xs_u32[b] + (unsigned)(r * XSTR + k0) * 4u;
            asm volatile("cp.async.cg.shared.global [%0], [%1], 16, %2;"
                         :: "r"(daddr), "l"(src), "r"(ssize));
        }
        #pragma unroll
        for (int j = 0; j < 2; j++) {
            int v = tid + j * 256;
            int r = (v * 4) / N;
            int cc = (v * 4) % N;
            const float* src = Wl + (size_t)(kc + r) * N + cc;
            unsigned daddr = ws_u32[b] + (unsigned)(r * N + cc) * 4u;
            asm volatile("cp.async.cg.shared.global [%0], [%1], 16;"
                         :: "r"(daddr), "l"(src));
        }
    };

    unsigned long long accv[4][4];
    #pragma unroll
    for (int i = 0; i < 4; i++)
        #pragma unroll
        for (int q = 0; q < 4; q++) accv[i][q] = 0ull;

    stage(0, 0);
    asm volatile("cp.async.commit_group;");
    for (int c = 0; c < 2; c++) {
        int buf = c & 1;
        if (c + 1 < 2) {
            stage(1, 1);
            asm volatile("cp.async.commit_group;");
            asm volatile("cp.async.wait_group 1;");
        } else {
            asm volatile("cp.async.wait_group 0;");
        }
        __syncthreads();
        const float* Xc = Xsb[buf];
        const float* Wc = Wsb[buf];
        #pragma unroll
        for (int k = 0; k < 32; k++) {
            unsigned long long a[4];
            #pragma unroll
            for (int i = 0; i < 4; i++) {
                unsigned a32 = *(const unsigned*)&Xc[(ty + 32 * i) * XSTR + k];
                asm("mov.b64 %0, {%1, %1};" : "=l"(a[i]) : "r"(a32));
            }
            #pragma unroll
            for (int h = 0; h < 2; h++) {
                ulonglong2 wp = *(const ulonglong2*)&Wc[k * N + tx * 8 + h * 4];
                #pragma unroll
                for (int i = 0; i < 4; i++) {
                    asm("fma.rn.f32x2 %0, %1, %2, %0;"
                        : "+l"(accv[i][2 * h]) : "l"(a[i]), "l"(wp.x));
                    asm("fma.rn.f32x2 %0, %1, %2, %0;"
                        : "+l"(accv[i][2 * h + 1]) : "l"(a[i]), "l"(wp.y));
                }
            }
        }
        __syncthreads();
    }

    // stage-1 epilogue: xp1 tile -> smem
    #pragma unroll
    for (int i = 0; i < 4; i++) {
        int r = ty + 32 * i;
        int row = base + r;
        bool ok = (row < M);
        #pragma unroll
        for (int q = 0; q < 4; q++) {
            float2 v = *(float2*)&accv[i][q];
            int col = tx * 8 + 2 * q;
            if (ok) {
                float2 a2 = *(const float2*)&P[(size_t)row * 64 + col];
                float2 ba = *(const float2*)&b0[col];
                float2 bb = *(const float2*)&b1[col];
                v.x = fmaxf(v.x + a2.x + ba.x + bb.x, 0.f);
                v.y = fmaxf(v.y + a2.y + ba.y + bb.y, 0.f);
            } else {
                v.x = 0.f; v.y = 0.f;
            }
            *(float2*)&tile[r * TSTR + col] = v;
        }
    }
    #pragma unroll
    for (int j = 0; j < 4; j++) {
        int v = tid + j * 256;
        ((float4*)W2)[v] = ((const float4*)Ws1)[v];
    }
    __syncthreads();

    // stage 2: XS1 = tile @ Ws1 (fp16 out), fused dot (fp32)
    unsigned long long acc2[4][4];
    #pragma unroll
    for (int i = 0; i < 4; i++)
        #pragma unroll
        for (int q = 0; q < 4; q++) acc2[i][q] = 0ull;
    #pragma unroll 4
    for (int k = 0; k < 64; k++) {
        unsigned long long a[4];
        #pragma unroll
        for (int i = 0; i < 4; i++) {
            unsigned a32 = *(const unsigned*)&tile[(ty + 32 * i) * TSTR + k];
            asm("mov.b64 %0, {%1, %1};" : "=l"(a[i]) : "r"(a32));
        }
        #pragma unroll
        for (int h = 0; h < 2; h++) {
            ulonglong2 wp = *(const ulonglong2*)&W2[k * 64 + tx * 8 + h * 4];
            #pragma unroll
            for (int i = 0; i < 4; i++) {
                asm("fma.rn.f32x2 %0, %1, %2, %0;"
                    : "+l"(acc2[i][2 * h]) : "l"(a[i]), "l"(wp.x));
                asm("fma.rn.f32x2 %0, %1, %2, %0;"
                    : "+l"(acc2[i][2 * h + 1]) : "l"(a[i]), "l"(wp.y));
            }
        }
    }
    #pragma unroll
    for (int i = 0; i < 4; i++) {
        int row = base + ty + 32 * i;
        if (row >= M) continue;
        float d = 0.f;
        #pragma unroll
        for (int q = 0; q < 4; q++) {
            float2 v = *(float2*)&acc2[i][q];
            int col = tx * 8 + 2 * q;
            *(__half2*)&XS1[(size_t)row * 64 + col] = __floats2half2_rn(v.x, v.y);
            float2 w2 = *(const float2*)&av[col];
            d += v.x * w2.x + v.y * w2.y;
        }
        #pragma unroll
        for (int o = 1; o < 8; o <<= 1) d += __shfl_xor_sync(0xFFFFFFFFu, d, o);
        if (tx == 0) dotout[row] = d;
    }
}

// ---------------- host ----------------
static inline int cdiv(long long a, int b) { return (int)((a + b - 1) / b); }

extern "C" void kernel_launch(void* const* d_in, const int* in_sizes, int n_in,
                              void* d_out, int out_size) {
    const float* xp       = (const float*)d_in[0];
    const float* xa       = (const float*)d_in[1];
    const float* gcn_W0   = (const float*)d_in[2];
    const float* gcn_b0   = (const float*)d_in[3];
    const float* sage_Wl0 = (const float*)d_in[4];
    const float* sage_bl0 = (const float*)d_in[5];
    const float* sage_Wr0 = (const float*)d_in[6];
    const float* gat_Ws0  = (const float*)d_in[7];
    const float* gat_Wd0  = (const float*)d_in[8];
    const float* gat_as0  = (const float*)d_in[9];
    const float* gat_ad0  = (const float*)d_in[10];
    const float* gat_b0   = (const float*)d_in[11];
    const float* gat_Ws1  = (const float*)d_in[17];
    const float* gat_Wd1  = (const float*)d_in[18];
    const float* gat_as1  = (const float*)d_in[19];
    const float* gat_ad1  = (const float*)d_in[20];
    const float* gat_b1   = (const float*)d_in[21];
    const float* lin_W    = (const float*)d_in[22];
    const float* lin_b    = (const float*)d_in[23];
    const int* cs = (const int*)d_in[24];
    const int* cd = (const int*)d_in[25];
    const int* ws = (const int*)d_in[26];  // author idx of writes edge
    const int* wd = (const int*)d_in[27];  // paper idx of writes edge
    float* out = (float*)d_out;

    void* p;
    #define SYM(name) cudaGetSymbolAddress(&p, g_##name)
    SYM(xls16); __half* xls16 = (__half*)p;
    SYM(XS16);  __half* XS16  = (__half*)p;
    SYM(XS116); __half* XS116 = (__half*)p;
    SYM(P);     float* P    = (float*)p;
    SYM(SA);    float* SA   = (float*)p;
    SYM(XD);    float* XD   = (float*)p;
    SYM(xa1);   float* xa1  = (float*)p;
    SYM(Wcat);  float* Wcat = (float*)p;
    SYM(dis);   float* dis  = (float*)p;
    SYM(asrc);  float* asrc = (float*)p;
    SYM(adst);  float* adst = (float*)p;
    SYM(asrc1); float* asrc1 = (float*)p;
    SYM(adst1); float* adst1 = (float*)p;
    SYM(degC); int* degC = (int*)p;
    SYM(degWp); int* degWp = (int*)p;
    SYM(degWa); int* degWa = (int*)p;
    SYM(offC); int* offC = (int*)p;
    SYM(offWp); int* offWp = (int*)p;
    SYM(offWa); int* offWa = (int*)p;
    SYM(curC); int* curC = (int*)p;
    SYM(curWp); int* curWp = (int*)p;
    SYM(curWa); int* curWa = (int*)p;
    SYM(bsumA); int* bsumA = (int*)p;
    SYM(bsumB); int* bsumB = (int*)p;
    SYM(csrC); int* csrC = (int*)p;
    SYM(csrWp); int* csrWp = (int*)p;
    SYM(csrWa); int* csrWa = (int*)p;
    #undef SYM

    cudaFuncSetAttribute(k_gemmF,
        cudaFuncAttributeMaxDynamicSharedMemorySize, gemmF_smem_bytes());
    cudaFuncSetAttribute(k_gemmC,
        cudaFuncAttributeMaxDynamicSharedMemorySize, gemmC_smem_bytes());
    cudaFuncSetAttribute(k_gemm2<64, 64, M_DOT>,
        cudaFuncAttributeMaxDynamicSharedMemorySize, gemm_smem_bytes<64, 64>());
    cudaFuncSetAttribute(k_gemm2<64, 32, M_BIAS>,
        cudaFuncAttributeMaxDynamicSharedMemorySize, gemm_smem_bytes<64, 32>());

    const int T = 256;
    cudaStream_t s0 = 0, sA, sB;
    cudaStreamCreateWithFlags(&sA, cudaStreamNonBlocking);
    cudaStreamCreateWithFlags(&sB, cudaStreamNonBlocking);
    cudaEvent_t eF, eG2, eG4, eSA, eGcn, eAuth;
    cudaEventCreateWithFlags(&eF,   cudaEventDisableTiming);
    cudaEventCreateWithFlags(&eG2,  cudaEventDisableTiming);
    cudaEventCreateWithFlags(&eG4,  cudaEventDisableTiming);
    cudaEventCreateWithFlags(&eSA,  cudaEventDisableTiming);
    cudaEventCreateWithFlags(&eGcn, cudaEventDisableTiming);
    cudaEventCreateWithFlags(&eAuth, cudaEventDisableTiming);

    #define GEMM(Kk, Nn, MODE, STRM, Xs, Ws_, B0, AV, DOT, Yy, Mm) \
        k_gemm2<Kk, Nn, MODE><<<cdiv(Mm, 128), 256, (gemm_smem_bytes<Kk, Nn>()), STRM>>>( \
            Xs, Ws_, B0, AV, DOT, Yy, Mm)

    // ================= fork (R12 schedule) =================
    cudaEventRecord(eF, s0);
    cudaStreamWaitEvent(sA, eF, 0);
    cudaStreamWaitEvent(sB, eF, 0);

    // ---- s0: fused layer-0 paper GEMM, then XD0 ----
    k_wcat<<<cdiv(128 * 192, T), T, 0, s0>>>(gcn_W0, sage_Wr0, gat_Ws0, Wcat);
    k_gemmF<<<cdiv(NP, 64), 256, gemmF_smem_bytes(), s0>>>(
        xp, Wcat, gat_as0, asrc, xls16, P, XS16, NP);
    cudaEventRecord(eG2, s0);   // xls16 + P + XS16 + asrc ready
    GEMM(64, 64, M_DOT, s0, xa, gat_Wd0, nullptr, gat_ad0, adst, XD, NA);
    cudaEventRecord(eG4, s0);

    // ---- sA: cites CSR build, then gcn_gather ----
    k_zero_i<<<cdiv(NP, T), T, 0, sA>>>(degC, NP);
    k_count<<<cdiv(EC, T), T, 0, sA>>>(cd, degC, EC);
    k_dis<<<cdiv(NP, T), T, 0, sA>>>(degC, dis, NP);
    k_scan1<<<cdiv(NP, 512), 512, 0, sA>>>(degC, offC, bsumA, NP);
    k_scan2<<<1, 512, 0, sA>>>(bsumA, cdiv(NP, 512));
    k_scan3<<<cdiv(NP, T), T, 0, sA>>>(offC, curC, bsumA, NP);
    k_fill<<<cdiv(EC, T), T, 0, sA>>>(cd, cs, curC, csrC, EC);
    cudaStreamWaitEvent(sA, eG2, 0);
    k_gcn_gather<<<cdiv((long long)NP * 32, T), T, 0, sA>>>(
        offC, csrC, (const __half2*)xls16, dis, P, NP, EC);
    cudaEventRecord(eGcn, sA);

    // ---- sB: writes CSRs; sage_gather; author branch ----
    k_zero_i<<<cdiv(NP, T), T, 0, sB>>>(degWp, NP);
    k_count<<<cdiv(EW, T), T, 0, sB>>>(wd, degWp, EW);
    k_scan1<<<cdiv(NP, 512), 512, 0, sB>>>(degWp, offWp, bsumB, NP);
    k_scan2<<<1, 512, 0, sB>>>(bsumB, cdiv(NP, 512));
    k_scan3<<<cdiv(NP, T), T, 0, sB>>>(offWp, curWp, bsumB, NP);
    k_fill<<<cdiv(EW, T), T, 0, sB>>>(wd, ws, curWp, csrWp, EW);
    k_sage_gather<<<cdiv((long long)NP * 32, T), T, 0, sB>>>(offWp, csrWp, xa, SA, NP, EW);
    cudaEventRecord(eSA, sB);
    k_zero_i<<<cdiv(NA, T), T, 0, sB>>>(degWa, NA);
    k_count<<<cdiv(EW, T), T, 0, sB>>>(ws, degWa, EW);
    k_scan1<<<cdiv(NA, 512), 512, 0, sB>>>(degWa, offWa, bsumB, NA);
    k_scan2<<<1, 512, 0, sB>>>(bsumB, cdiv(NA, 512));
    k_scan3<<<cdiv(NA, T), T, 0, sB>>>(offWa, curWa, bsumB, NA);
    k_fill<<<cdiv(EW, T), T, 0, sB>>>(ws, wd, curWa, csrWa, EW);
    cudaStreamWaitEvent(sB, eG4, 0);
    k_gat_gather<<<cdiv((long long)NA * 32, T), T, 0, sB>>>(
        offWa, csrWa, asrc, adst, (const __half2*)XS16, gat_b0, xa1, NA, EW);
    GEMM(64, 64, M_DOT, sB, xa1, gat_Wd1, nullptr, gat_ad1, adst1, XD, NA);
    cudaEventRecord(eAuth, sB);

    // ---- s0 (paper branch): fused comb+XS1, then final GAT + head ----
    cudaStreamWaitEvent(s0, eSA, 0);
    cudaStreamWaitEvent(s0, eGcn, 0);
    k_gemmC<<<cdiv(NP, 128), 256, gemmC_smem_bytes(), s0>>>(
        SA, sage_Wl0, gcn_b0, sage_bl0, P, gat_Ws1, gat_as1, asrc1, XS116, NP);
    cudaStreamWaitEvent(s0, eAuth, 0);
    k_gat_gather<<<cdiv((long long)NA * 32, T), T, 0, s0>>>(
        offWa, csrWa, asrc1, adst1, (const __half2*)XS116, gat_b1, xa1, NA, EW);
    GEMM(64, 32, M_BIAS, s0, xa1, lin_W, lin_b, nullptr, nullptr, out, NA);
    #undef GEMM

    // destroy only outside capture
    cudaStreamCaptureStatus st = cudaStreamCaptureStatusNone;
    cudaStreamIsCapturing(sA, &st);
    if (st == cudaStreamCaptureStatusNone) {
        cudaEventDestroy(eF);  cudaEventDestroy(eG2); cudaEventDestroy(eG4);
        cudaEventDestroy(eSA); cudaEventDestroy(eGcn); cudaEventDestroy(eAuth);
        cudaStreamDestroy(sA); cudaStreamDestroy(sB);
    }
}